// round 2
// baseline (speedup 1.0000x reference)
#include <cuda_runtime.h>
#include <cuda_bf16.h>
#include <math.h>

// Problem constants
#define NB     64
#define LL     196
#define HID    768
#define FF     3072
#define NH     24
#define HD     32
#define M_ROWS (NB * LL)          // 12544
#define SROW   33                 // padded head-dim stride in smem
#define RATE_F 0.2f

// ---------------- scratch (static device globals; no runtime allocation) ----
__device__ float g_ln[(size_t)M_ROWS * HID];
__device__ float g_q [(size_t)M_ROWS * HID];
__device__ float g_k [(size_t)M_ROWS * HID];
__device__ float g_v [(size_t)M_ROWS * HID];
__device__ float g_o [(size_t)M_ROWS * HID];
__device__ float g_h [(size_t)M_ROWS * FF];

// ---------------------------------------------------------------- LayerNorm
__global__ __launch_bounds__(256) void ln_kernel(
    const float* __restrict__ x, const float* __restrict__ g,
    const float* __restrict__ b, float* __restrict__ y)
{
    __shared__ float sm8[8];
    __shared__ float sstat;
    const int row = blockIdx.x, tid = threadIdx.x;
    const float* xr = x + (size_t)row * HID;
    float v0 = xr[tid], v1 = xr[tid + 256], v2 = xr[tid + 512];
    float s = v0 + v1 + v2;
    #pragma unroll
    for (int off = 16; off; off >>= 1) s += __shfl_xor_sync(0xffffffffu, s, off);
    if ((tid & 31) == 0) sm8[tid >> 5] = s;
    __syncthreads();
    if (tid == 0) {
        float t = 0.f;
        #pragma unroll
        for (int i = 0; i < 8; i++) t += sm8[i];
        sstat = t * (1.0f / HID);
    }
    __syncthreads();
    const float mu = sstat;
    float d0 = v0 - mu, d1 = v1 - mu, d2 = v2 - mu;
    float q = d0 * d0 + d1 * d1 + d2 * d2;
    #pragma unroll
    for (int off = 16; off; off >>= 1) q += __shfl_xor_sync(0xffffffffu, q, off);
    __syncthreads();
    if ((tid & 31) == 0) sm8[tid >> 5] = q;
    __syncthreads();
    if (tid == 0) {
        float t = 0.f;
        #pragma unroll
        for (int i = 0; i < 8; i++) t += sm8[i];
        sstat = rsqrtf(t * (1.0f / HID) + 1e-5f);
    }
    __syncthreads();
    const float r = sstat;
    float* yr = y + (size_t)row * HID;
    yr[tid]       = d0 * r * g[tid]       + b[tid];
    yr[tid + 256] = d1 * r * g[tid + 256] + b[tid + 256];
    yr[tid + 512] = d2 * r * g[tid + 512] + b[tid + 512];
}

// --------------------------------------------------- per-head QKV projection
// q[r, h*32+e] = sum_d ln[r, h*32+d] * wq[e, d]   (weights shared across heads)
__global__ __launch_bounds__(256) void qkv_kernel(
    const float* __restrict__ xln,
    const float* __restrict__ wq, const float* __restrict__ wk,
    const float* __restrict__ wv,
    float* __restrict__ q, float* __restrict__ k_, float* __restrict__ v)
{
    __shared__ float xs[HID];
    __shared__ float ws[3][32][33];   // padded: avoid 32-way conflicts
    const int row = blockIdx.x, tid = threadIdx.x;
    for (int t = tid; t < HID; t += 256) xs[t] = xln[(size_t)row * HID + t];
    for (int t = tid; t < 1024; t += 256) {
        const int e = t >> 5, d = t & 31;
        ws[0][e][d] = wq[t];
        ws[1][e][d] = wk[t];
        ws[2][e][d] = wv[t];
    }
    __syncthreads();
    for (int t = tid; t < 3 * HID; t += 256) {
        const int m = t / HID, r = t % HID;
        const int hh = r >> 5, e = r & 31;
        const float* xp = xs + (hh << 5);
        const float* wp = &ws[m][e][0];
        float s = 0.f;
        #pragma unroll
        for (int d = 0; d < 32; d++) s = fmaf(xp[d], wp[d], s);
        float* out = (m == 0) ? q : ((m == 1) ? k_ : v);
        out[(size_t)row * HID + r] = s;
    }
}

// ------------------------------------------------------------------ attention
// One block per (n, h). Full 196x196 scores per block, staged tiles in smem.
__global__ __launch_bounds__(256) void attn_kernel(
    const float* __restrict__ q, const float* __restrict__ k,
    const float* __restrict__ v, const float* __restrict__ rel_bias,
    float* __restrict__ o)
{
    extern __shared__ float sm[];
    float* qs   = sm;                    // LL * SROW
    float* ks   = qs + LL * SROW;
    float* vs   = ks + LL * SROW;
    float* bs   = vs + LL * SROW;        // 784
    float* sbuf = bs + 784;              // 8 * LL

    const int nb = blockIdx.x;
    const int n = nb / NH, h = nb % NH;
    const int tid = threadIdx.x, lane = tid & 31, wid = tid >> 5;
    const size_t base = (size_t)n * LL * HID + (size_t)h * HD;

    for (int t = tid; t < LL * HD; t += 256) {
        const int l = t >> 5, d = t & 31;
        const size_t g = base + (size_t)l * HID + d;
        qs[l * SROW + d] = q[g];
        ks[l * SROW + d] = k[g];
        vs[l * SROW + d] = v[g];
    }
    for (int t = tid; t < 784; t += 256) bs[t] = rel_bias[t];
    __syncthreads();

    const float scale = 0.17677669529663687f;  // 1/sqrt(32)
    float* srow = sbuf + wid * LL;

    for (int qr = wid; qr < LL; qr += 8) {
        const int qi = qr / 14, qj = qr % 14;
        const float* qp = qs + qr * SROW;
        float mx = -1e30f;
        for (int kk = lane; kk < LL; kk += 32) {
            const float* kp = ks + kk * SROW;
            float s = 0.f;
            #pragma unroll
            for (int d = 0; d < 32; d++) s = fmaf(qp[d], kp[d], s);
            const int ki = kk / 14, kj = kk % 14;
            const int bidx = (qi - ki + 14) * 28 + (qj - kj + 14);
            s = (s + bs[bidx]) * scale;
            srow[kk] = s;
            mx = fmaxf(mx, s);
        }
        #pragma unroll
        for (int off = 16; off; off >>= 1)
            mx = fmaxf(mx, __shfl_xor_sync(0xffffffffu, mx, off));
        float sum = 0.f;
        for (int kk = lane; kk < LL; kk += 32) {
            const float e = __expf(srow[kk] - mx);
            srow[kk] = e;
            sum += e;
        }
        #pragma unroll
        for (int off = 16; off; off >>= 1)
            sum += __shfl_xor_sync(0xffffffffu, sum, off);
        const float inv = 1.0f / sum;
        __syncwarp();
        float acc = 0.f;
        #pragma unroll 4
        for (int kk = 0; kk < LL; kk++)
            acc = fmaf(srow[kk], vs[kk * SROW + lane], acc);
        o[base + (size_t)qr * HID + lane] = acc * inv;
        __syncwarp();
    }
}

// --------------------------------------------------------------------- GEMM
// C[M,N] = A[M,K] @ B[N,K]^T  (+bias) with epilogue modes:
//   mode 0: plain   mode 1: exact gelu   mode 2: (resid + val) * rate
#define GBM 128
#define GBN 128
#define GBK 8
#define GPAD 132

__global__ __launch_bounds__(256) void gemm_nt_kernel(
    const float* __restrict__ A, const float* __restrict__ B,
    const float* __restrict__ bias, const float* __restrict__ resid,
    float* __restrict__ C, int M, int N, int K, int mode, float rate)
{
    __shared__ float As[GBK][GPAD];
    __shared__ float Bs[GBK][GPAD];
    const int bm = blockIdx.y * GBM, bn = blockIdx.x * GBN;
    const int tid = threadIdx.x;
    const int tm = (tid >> 4) << 3;
    const int tn = (tid & 15) << 3;
    float acc[8][8] = {};

    for (int k0 = 0; k0 < K; k0 += GBK) {
        #pragma unroll
        for (int i = 0; i < 4; i++) {
            const int idx = tid + i * 256;
            const int r = idx >> 3, c = idx & 7;
            As[c][r] = A[(size_t)(bm + r) * K + k0 + c];
            Bs[c][r] = B[(size_t)(bn + r) * K + k0 + c];
        }
        __syncthreads();
        #pragma unroll
        for (int k = 0; k < GBK; k++) {
            float a[8], b[8];
            #pragma unroll
            for (int i = 0; i < 8; i++) a[i] = As[k][tm + i];
            #pragma unroll
            for (int j = 0; j < 8; j++) b[j] = Bs[k][tn + j];
            #pragma unroll
            for (int i = 0; i < 8; i++)
                #pragma unroll
                for (int j = 0; j < 8; j++)
                    acc[i][j] = fmaf(a[i], b[j], acc[i][j]);
        }
        __syncthreads();
    }

    #pragma unroll
    for (int i = 0; i < 8; i++) {
        const int row = bm + tm + i;
        #pragma unroll
        for (int j = 0; j < 8; j++) {
            const int col = bn + tn + j;
            float vv = acc[i][j];
            if (bias) vv += bias[col];
            if (mode == 1) {
                vv = 0.5f * vv * (1.0f + erff(vv * 0.70710678118654752f));
            } else if (mode == 2) {
                vv = (resid[(size_t)row * N + col] + vv) * rate;
            }
            C[(size_t)row * N + col] = vv;
        }
    }
}

// --------------------------------------------------------------------- host
extern "C" void kernel_launch(void* const* d_in, const int* in_sizes, int n_in,
                              void* d_out, int out_size)
{
    const float* x        = (const float*)d_in[0];
    const float* rel_bias = (const float*)d_in[1];
    const float* wq       = (const float*)d_in[2];
    const float* wk       = (const float*)d_in[3];
    const float* wv       = (const float*)d_in[4];
    const float* w_out    = (const float*)d_in[5];
    const float* ln1_g    = (const float*)d_in[6];
    const float* ln1_b    = (const float*)d_in[7];
    const float* ln2_g    = (const float*)d_in[8];
    const float* ln2_b    = (const float*)d_in[9];
    const float* w1       = (const float*)d_in[10];
    const float* b1       = (const float*)d_in[11];
    const float* w2       = (const float*)d_in[12];
    const float* b2       = (const float*)d_in[13];
    float* out = (float*)d_out;

    float *p_ln, *p_q, *p_k, *p_v, *p_o, *p_h;
    cudaGetSymbolAddress((void**)&p_ln, g_ln);
    cudaGetSymbolAddress((void**)&p_q,  g_q);
    cudaGetSymbolAddress((void**)&p_k,  g_k);
    cudaGetSymbolAddress((void**)&p_v,  g_v);
    cudaGetSymbolAddress((void**)&p_o,  g_o);
    cudaGetSymbolAddress((void**)&p_h,  g_h);

    const int attn_smem = (3 * LL * SROW + 784 + 8 * LL) * sizeof(float);
    cudaFuncSetAttribute(attn_kernel,
                         cudaFuncAttributeMaxDynamicSharedMemorySize, attn_smem);

    // 1) ln1
    ln_kernel<<<M_ROWS, 256>>>(x, ln1_g, ln1_b, p_ln);
    // 2) q/k/v head projections
    qkv_kernel<<<M_ROWS, 256>>>(p_ln, wq, wk, wv, p_q, p_k, p_v);
    // 3) attention
    attn_kernel<<<NB * NH, 256, attn_smem>>>(p_q, p_k, p_v, rel_bias, p_o);
    // 4) output projection + residual + rate  -> d_out holds x1
    {
        dim3 grid(HID / GBN, M_ROWS / GBM);
        gemm_nt_kernel<<<grid, 256>>>(p_o, w_out, nullptr, x, out,
                                      M_ROWS, HID, HID, 2, RATE_F);
    }
    // 5) ln2
    ln_kernel<<<M_ROWS, 256>>>(out, ln2_g, ln2_b, p_ln);
    // 6) ffn1 + gelu
    {
        dim3 grid(FF / GBN, M_ROWS / GBM);
        gemm_nt_kernel<<<grid, 256>>>(p_ln, w1, b1, nullptr, p_h,
                                      M_ROWS, FF, HID, 1, 0.f);
    }
    // 7) ffn2 + residual + rate -> d_out final
    {
        dim3 grid(HID / GBN, M_ROWS / GBM);
        gemm_nt_kernel<<<grid, 256>>>(p_h, w2, b2, out, out,
                                      M_ROWS, HID, FF, 2, RATE_F);
    }
}

// round 4
// speedup vs baseline: 2.2149x; 2.2149x over previous
#include <cuda_runtime.h>
#include <cuda_bf16.h>
#include <math.h>
#include <stdint.h>

// Problem constants
#define NB     64
#define LL     196
#define HID    768
#define FF     3072
#define NH     24
#define HD     32
#define M_ROWS (NB * LL)          // 12544
#define SROW   33                 // padded head-dim stride in smem (attention)
#define RATE_F 0.2f

// ---------------- scratch (static device globals; no runtime allocation) ----
__device__ float g_ln[(size_t)M_ROWS * HID];
__device__ float g_q [(size_t)M_ROWS * HID];
__device__ float g_k [(size_t)M_ROWS * HID];
__device__ float g_v [(size_t)M_ROWS * HID];
__device__ float g_o [(size_t)M_ROWS * HID];
__device__ float g_h [(size_t)M_ROWS * FF];

// ---------------------------------------------------------------- LayerNorm
__global__ __launch_bounds__(256) void ln_kernel(
    const float* __restrict__ x, const float* __restrict__ g,
    const float* __restrict__ b, float* __restrict__ y)
{
    __shared__ float sm8[8];
    __shared__ float sstat;
    const int row = blockIdx.x, tid = threadIdx.x;
    const float* xr = x + (size_t)row * HID;
    float v0 = xr[tid], v1 = xr[tid + 256], v2 = xr[tid + 512];
    float s = v0 + v1 + v2;
    #pragma unroll
    for (int off = 16; off; off >>= 1) s += __shfl_xor_sync(0xffffffffu, s, off);
    if ((tid & 31) == 0) sm8[tid >> 5] = s;
    __syncthreads();
    if (tid == 0) {
        float t = 0.f;
        #pragma unroll
        for (int i = 0; i < 8; i++) t += sm8[i];
        sstat = t * (1.0f / HID);
    }
    __syncthreads();
    const float mu = sstat;
    float d0 = v0 - mu, d1 = v1 - mu, d2 = v2 - mu;
    float q = d0 * d0 + d1 * d1 + d2 * d2;
    #pragma unroll
    for (int off = 16; off; off >>= 1) q += __shfl_xor_sync(0xffffffffu, q, off);
    __syncthreads();
    if ((tid & 31) == 0) sm8[tid >> 5] = q;
    __syncthreads();
    if (tid == 0) {
        float t = 0.f;
        #pragma unroll
        for (int i = 0; i < 8; i++) t += sm8[i];
        sstat = rsqrtf(t * (1.0f / HID) + 1e-5f);
    }
    __syncthreads();
    const float r = sstat;
    float* yr = y + (size_t)row * HID;
    yr[tid]       = d0 * r * g[tid]       + b[tid];
    yr[tid + 256] = d1 * r * g[tid + 256] + b[tid + 256];
    yr[tid + 512] = d2 * r * g[tid + 512] + b[tid + 512];
}

// --------------------------------------------------- per-head QKV projection
__global__ __launch_bounds__(256) void qkv_kernel(
    const float* __restrict__ xln,
    const float* __restrict__ wq, const float* __restrict__ wk,
    const float* __restrict__ wv,
    float* __restrict__ q, float* __restrict__ k_, float* __restrict__ v)
{
    __shared__ float xs[HID];
    __shared__ float ws[3][32][33];
    const int row = blockIdx.x, tid = threadIdx.x;
    for (int t = tid; t < HID; t += 256) xs[t] = xln[(size_t)row * HID + t];
    for (int t = tid; t < 1024; t += 256) {
        const int e = t >> 5, d = t & 31;
        ws[0][e][d] = wq[t];
        ws[1][e][d] = wk[t];
        ws[2][e][d] = wv[t];
    }
    __syncthreads();
    for (int t = tid; t < 3 * HID; t += 256) {
        const int m = t / HID, r = t % HID;
        const int hh = r >> 5, e = r & 31;
        const float* xp = xs + (hh << 5);
        const float* wp = &ws[m][e][0];
        float s = 0.f;
        #pragma unroll
        for (int d = 0; d < 32; d++) s = fmaf(xp[d], wp[d], s);
        float* out = (m == 0) ? q : ((m == 1) ? k_ : v);
        out[(size_t)row * HID + r] = s;
    }
}

// ------------------------------------------------------------------ attention
__global__ __launch_bounds__(256) void attn_kernel(
    const float* __restrict__ q, const float* __restrict__ k,
    const float* __restrict__ v, const float* __restrict__ rel_bias,
    float* __restrict__ o)
{
    extern __shared__ float sm[];
    float* qs   = sm;
    float* ks   = qs + LL * SROW;
    float* vs   = ks + LL * SROW;
    float* bs   = vs + LL * SROW;
    float* sbuf = bs + 784;

    const int nb = blockIdx.x;
    const int n = nb / NH, h = nb % NH;
    const int tid = threadIdx.x, lane = tid & 31, wid = tid >> 5;
    const size_t base = (size_t)n * LL * HID + (size_t)h * HD;

    for (int t = tid; t < LL * HD; t += 256) {
        const int l = t >> 5, d = t & 31;
        const size_t g = base + (size_t)l * HID + d;
        qs[l * SROW + d] = q[g];
        ks[l * SROW + d] = k[g];
        vs[l * SROW + d] = v[g];
    }
    for (int t = tid; t < 784; t += 256) bs[t] = rel_bias[t];
    __syncthreads();

    const float scale = 0.17677669529663687f;
    float* srow = sbuf + wid * LL;

    for (int qr = wid; qr < LL; qr += 8) {
        const int qi = qr / 14, qj = qr % 14;
        const float* qp = qs + qr * SROW;
        float mx = -1e30f;
        for (int kk = lane; kk < LL; kk += 32) {
            const float* kp = ks + kk * SROW;
            float s = 0.f;
            #pragma unroll
            for (int d = 0; d < 32; d++) s = fmaf(qp[d], kp[d], s);
            const int ki = kk / 14, kj = kk % 14;
            const int bidx = (qi - ki + 14) * 28 + (qj - kj + 14);
            s = (s + bs[bidx]) * scale;
            srow[kk] = s;
            mx = fmaxf(mx, s);
        }
        #pragma unroll
        for (int off = 16; off; off >>= 1)
            mx = fmaxf(mx, __shfl_xor_sync(0xffffffffu, mx, off));
        float sum = 0.f;
        for (int kk = lane; kk < LL; kk += 32) {
            const float e = __expf(srow[kk] - mx);
            srow[kk] = e;
            sum += e;
        }
        #pragma unroll
        for (int off = 16; off; off >>= 1)
            sum += __shfl_xor_sync(0xffffffffu, sum, off);
        const float inv = 1.0f / sum;
        __syncwarp();
        float acc = 0.f;
        #pragma unroll 4
        for (int kk = 0; kk < LL; kk++)
            acc = fmaf(srow[kk], vs[kk * SROW + lane], acc);
        o[base + (size_t)qr * HID + lane] = acc * inv;
        __syncwarp();
    }
}

// ------------------------------------------------------------ tf32 TC GEMM
// C[M,N] = A[M,K] @ B[N,K]^T (+bias), epilogue modes:
//   0: plain   1: exact gelu   2: (resid + val) * rate
// Block 128x128, 4 warps of 64x64, k-tile 32, cp.async double buffer.
#define TBM 128
#define TBN 128
#define TBK 32
#define TSTRIDE 36   // floats per smem row (32 data + 4 pad); conflict-free frags

__device__ __forceinline__ uint32_t f2tf(float f) {
    uint32_t r;
    asm("cvt.rna.tf32.f32 %0, %1;" : "=r"(r) : "f"(f));
    return r;
}

__device__ __forceinline__ void mma_tf32(
    float* c, uint32_t a0, uint32_t a1, uint32_t a2, uint32_t a3,
    uint32_t b0, uint32_t b1)
{
    asm volatile(
        "mma.sync.aligned.m16n8k8.row.col.f32.tf32.tf32.f32 "
        "{%0,%1,%2,%3}, {%4,%5,%6,%7}, {%8,%9}, {%0,%1,%2,%3};\n"
        : "+f"(c[0]), "+f"(c[1]), "+f"(c[2]), "+f"(c[3])
        : "r"(a0), "r"(a1), "r"(a2), "r"(a3), "r"(b0), "r"(b1));
}

#define CP_ASYNC16(dst, src) \
    asm volatile("cp.async.cg.shared.global [%0], [%1], 16;\n" :: "r"(dst), "l"(src))

__global__ __launch_bounds__(128) void gemm_tc_kernel(
    const float* __restrict__ A, const float* __restrict__ B,
    const float* __restrict__ bias, const float* __restrict__ resid,
    float* __restrict__ C, int M, int N, int K, int mode, float rate)
{
    extern __shared__ float smg[];
    const int stageFloats = 2 * TBM * TSTRIDE;    // 9216

    const int tid  = threadIdx.x;
    const int lane = tid & 31, warp = tid >> 5;
    const int wr = warp >> 1, wc = warp & 1;      // 2x2 warp grid
    const int bm = blockIdx.y * TBM, bn = blockIdx.x * TBN;

    const uint32_t smem_base = (uint32_t)__cvta_generic_to_shared(smg);

    const int nTiles = K / TBK;

    auto load_tile = [&](int kt, int s) {
        const float* Ag = A + (size_t)bm * K + (size_t)kt * TBK;
        const float* Bg = B + (size_t)bn * K + (size_t)kt * TBK;
        const uint32_t sA = smem_base + (uint32_t)(s * stageFloats) * 4u;
        const uint32_t sB = sA + (uint32_t)(TBM * TSTRIDE) * 4u;
        #pragma unroll
        for (int i = 0; i < 8; i++) {
            const int idx = i * 128 + tid;
            const int r = idx >> 3, c = idx & 7;
            CP_ASYNC16(sA + (uint32_t)(r * TSTRIDE * 4 + c * 16), Ag + (size_t)r * K + c * 4);
            CP_ASYNC16(sB + (uint32_t)(r * TSTRIDE * 4 + c * 16), Bg + (size_t)r * K + c * 4);
        }
    };

    float acc[4][8][4];
    #pragma unroll
    for (int i = 0; i < 4; i++)
        #pragma unroll
        for (int j = 0; j < 8; j++)
            #pragma unroll
            for (int r = 0; r < 4; r++) acc[i][j][r] = 0.f;

    const int aRow0 = wr * 64 + (lane >> 2);
    const int bRow0 = wc * 64 + (lane >> 2);
    const int kq = lane & 3;

    load_tile(0, 0);
    asm volatile("cp.async.commit_group;\n");

    for (int t = 0; t < nTiles; t++) {
        if (t + 1 < nTiles) {
            load_tile(t + 1, (t + 1) & 1);
            asm volatile("cp.async.commit_group;\n");
            asm volatile("cp.async.wait_group 1;\n");
        } else {
            asm volatile("cp.async.wait_group 0;\n");
        }
        __syncthreads();

        const float* As = smg + (t & 1) * stageFloats;
        const float* Bs = As + TBM * TSTRIDE;

        #pragma unroll
        for (int ks = 0; ks < 4; ks++) {
            const int kb = ks * 8 + kq;
            uint32_t bf[8][2];
            #pragma unroll
            for (int nt = 0; nt < 8; nt++) {
                const int rb = (bRow0 + nt * 8) * TSTRIDE + kb;
                bf[nt][0] = f2tf(Bs[rb]);
                bf[nt][1] = f2tf(Bs[rb + 4]);
            }
            #pragma unroll
            for (int mt = 0; mt < 4; mt++) {
                const int r0 = (aRow0 + mt * 16) * TSTRIDE + kb;
                const int r1 = r0 + 8 * TSTRIDE;
                const uint32_t a0 = f2tf(As[r0]);
                const uint32_t a1 = f2tf(As[r1]);
                const uint32_t a2 = f2tf(As[r0 + 4]);
                const uint32_t a3 = f2tf(As[r1 + 4]);
                #pragma unroll
                for (int nt = 0; nt < 8; nt++)
                    mma_tf32(acc[mt][nt], a0, a1, a2, a3, bf[nt][0], bf[nt][1]);
            }
        }
        __syncthreads();
    }

    // ------------------------------------------------------------- epilogue
    const int cRow0 = bm + wr * 64 + (lane >> 2);
    const int cCol0 = bn + wc * 64 + 2 * (lane & 3);
    #pragma unroll
    for (int mt = 0; mt < 4; mt++) {
        #pragma unroll
        for (int nt = 0; nt < 8; nt++) {
            #pragma unroll
            for (int half = 0; half < 2; half++) {
                const int row = cRow0 + mt * 16 + half * 8;
                #pragma unroll
                for (int e = 0; e < 2; e++) {
                    const int col = cCol0 + nt * 8 + e;
                    float vv = acc[mt][nt][half * 2 + e];
                    if (bias) vv += bias[col];
                    if (mode == 1) {
                        vv = 0.5f * vv * (1.0f + erff(vv * 0.70710678118654752f));
                    } else if (mode == 2) {
                        vv = (resid[(size_t)row * N + col] + vv) * rate;
                    }
                    C[(size_t)row * N + col] = vv;
                }
            }
        }
    }
}

// --------------------------------------------------------------------- host
extern "C" void kernel_launch(void* const* d_in, const int* in_sizes, int n_in,
                              void* d_out, int out_size)
{
    const float* x        = (const float*)d_in[0];
    const float* rel_bias = (const float*)d_in[1];
    const float* wq       = (const float*)d_in[2];
    const float* wk       = (const float*)d_in[3];
    const float* wv       = (const float*)d_in[4];
    const float* w_out    = (const float*)d_in[5];
    const float* ln1_g    = (const float*)d_in[6];
    const float* ln1_b    = (const float*)d_in[7];
    const float* ln2_g    = (const float*)d_in[8];
    const float* ln2_b    = (const float*)d_in[9];
    const float* w1       = (const float*)d_in[10];
    const float* b1       = (const float*)d_in[11];
    const float* w2       = (const float*)d_in[12];
    const float* b2       = (const float*)d_in[13];
    float* out = (float*)d_out;

    float *p_ln, *p_q, *p_k, *p_v, *p_o, *p_h;
    cudaGetSymbolAddress((void**)&p_ln, g_ln);
    cudaGetSymbolAddress((void**)&p_q,  g_q);
    cudaGetSymbolAddress((void**)&p_k,  g_k);
    cudaGetSymbolAddress((void**)&p_v,  g_v);
    cudaGetSymbolAddress((void**)&p_o,  g_o);
    cudaGetSymbolAddress((void**)&p_h,  g_h);

    const int attn_smem = (3 * LL * SROW + 784 + 8 * LL) * sizeof(float);
    cudaFuncSetAttribute(attn_kernel,
                         cudaFuncAttributeMaxDynamicSharedMemorySize, attn_smem);
    const int gemm_smem = 2 * 2 * TBM * TSTRIDE * (int)sizeof(float);  // 73728
    cudaFuncSetAttribute(gemm_tc_kernel,
                         cudaFuncAttributeMaxDynamicSharedMemorySize, gemm_smem);

    // 1) ln1
    ln_kernel<<<M_ROWS, 256>>>(x, ln1_g, ln1_b, p_ln);
    // 2) q/k/v head projections
    qkv_kernel<<<M_ROWS, 256>>>(p_ln, wq, wk, wv, p_q, p_k, p_v);
    // 3) attention
    attn_kernel<<<NB * NH, 256, attn_smem>>>(p_q, p_k, p_v, rel_bias, p_o);
    // 4) output projection + residual + rate -> d_out holds x1
    {
        dim3 grid(HID / TBN, M_ROWS / TBM);
        gemm_tc_kernel<<<grid, 128, gemm_smem>>>(p_o, w_out, nullptr, x, out,
                                                 M_ROWS, HID, HID, 2, RATE_F);
    }
    // 5) ln2
    ln_kernel<<<M_ROWS, 256>>>(out, ln2_g, ln2_b, p_ln);
    // 6) ffn1 + gelu
    {
        dim3 grid(FF / TBN, M_ROWS / TBM);
        gemm_tc_kernel<<<grid, 128, gemm_smem>>>(p_ln, w1, b1, nullptr, p_h,
                                                 M_ROWS, FF, HID, 1, 0.f);
    }
    // 7) ffn2 + residual + rate -> d_out final
    {
        dim3 grid(HID / TBN, M_ROWS / TBM);
        gemm_tc_kernel<<<grid, 128, gemm_smem>>>(p_h, w2, b2, out, out,
                                                 M_ROWS, HID, FF, 2, RATE_F);
    }
}

// round 5
// speedup vs baseline: 2.9593x; 1.3361x over previous
#include <cuda_runtime.h>
#include <cuda_bf16.h>
#include <math.h>
#include <stdint.h>

// Problem constants
#define NB     64
#define LL     196
#define HID    768
#define FF     3072
#define NH     24
#define HD     32
#define M_ROWS (NB * LL)          // 12544
#define RATE_F 0.2f
#define LPAD   208                // 196 padded to 13*16 (and 26*8)

// ---------------- scratch (static device globals; no runtime allocation) ----
__device__ float g_ln[(size_t)M_ROWS * HID];
__device__ float g_q [(size_t)M_ROWS * HID];
__device__ float g_k [(size_t)M_ROWS * HID];
__device__ float g_v [(size_t)M_ROWS * HID];
__device__ float g_o [(size_t)M_ROWS * HID];
__device__ float g_h [(size_t)M_ROWS * FF];
__device__ float g_wout_r[HID * HID];
__device__ float g_w1_r[FF * HID];
__device__ float g_w2_r[HID * FF];
__device__ float g_bias[LPAD * LPAD];

// ------------------------------------------------------------ tf32 helpers
__device__ __forceinline__ uint32_t f2tf(float f) {
    uint32_t r;
    asm("cvt.rna.tf32.f32 %0, %1;" : "=r"(r) : "f"(f));
    return r;
}
__device__ __forceinline__ float tf32r(float f) {
    return __uint_as_float(f2tf(f));
}
__device__ __forceinline__ void mma_tf32(
    float* c, uint32_t a0, uint32_t a1, uint32_t a2, uint32_t a3,
    uint32_t b0, uint32_t b1)
{
    asm volatile(
        "mma.sync.aligned.m16n8k8.row.col.f32.tf32.tf32.f32 "
        "{%0,%1,%2,%3}, {%4,%5,%6,%7}, {%8,%9}, {%0,%1,%2,%3};\n"
        : "+f"(c[0]), "+f"(c[1]), "+f"(c[2]), "+f"(c[3])
        : "r"(a0), "r"(a1), "r"(a2), "r"(a3), "r"(b0), "r"(b1));
}

// ----------------------------------------------------- weight pre-rounding
__global__ __launch_bounds__(256) void round_w_kernel(
    const float* __restrict__ w, float* __restrict__ out, int n)
{
    int i = blockIdx.x * 256 + threadIdx.x;
    if (i < n) out[i] = tf32r(w[i]);
}

// ----------------------------------------------------- bias matrix builder
__global__ __launch_bounds__(256) void bias_init_kernel(
    const float* __restrict__ rel_bias, float* __restrict__ bm)
{
    int idx = blockIdx.x * 256 + threadIdx.x;
    if (idx >= LPAD * LPAD) return;
    int row = idx / LPAD, col = idx % LPAD;
    float val = 0.f;
    if (row < LL && col < LL) {
        int qi = row / 14, qj = row % 14;
        int ki = col / 14, kj = col % 14;
        val = rel_bias[(qi - ki + 14) * 28 + (qj - kj + 14)];
    }
    bm[idx] = val;
}

// ---------------------------------------------------------------- LayerNorm
__global__ __launch_bounds__(256) void ln_kernel(
    const float* __restrict__ x, const float* __restrict__ g,
    const float* __restrict__ b, float* __restrict__ y)
{
    __shared__ float sm8[8];
    __shared__ float sstat;
    const int row = blockIdx.x, tid = threadIdx.x;
    const float* xr = x + (size_t)row * HID;
    float v0 = xr[tid], v1 = xr[tid + 256], v2 = xr[tid + 512];
    float s = v0 + v1 + v2;
    #pragma unroll
    for (int off = 16; off; off >>= 1) s += __shfl_xor_sync(0xffffffffu, s, off);
    if ((tid & 31) == 0) sm8[tid >> 5] = s;
    __syncthreads();
    if (tid == 0) {
        float t = 0.f;
        #pragma unroll
        for (int i = 0; i < 8; i++) t += sm8[i];
        sstat = t * (1.0f / HID);
    }
    __syncthreads();
    const float mu = sstat;
    float d0 = v0 - mu, d1 = v1 - mu, d2 = v2 - mu;
    float q = d0 * d0 + d1 * d1 + d2 * d2;
    #pragma unroll
    for (int off = 16; off; off >>= 1) q += __shfl_xor_sync(0xffffffffu, q, off);
    __syncthreads();
    if ((tid & 31) == 0) sm8[tid >> 5] = q;
    __syncthreads();
    if (tid == 0) {
        float t = 0.f;
        #pragma unroll
        for (int i = 0; i < 8; i++) t += sm8[i];
        sstat = rsqrtf(t * (1.0f / HID) + 1e-5f);
    }
    __syncthreads();
    const float r = sstat;
    float* yr = y + (size_t)row * HID;
    yr[tid]       = tf32r(d0 * r * g[tid]       + b[tid]);
    yr[tid + 256] = tf32r(d1 * r * g[tid + 256] + b[tid + 256]);
    yr[tid + 512] = tf32r(d2 * r * g[tid + 512] + b[tid + 512]);
}

// --------------------------------------------------- per-head QKV projection
__global__ __launch_bounds__(256) void qkv_kernel(
    const float* __restrict__ xln,
    const float* __restrict__ wq, const float* __restrict__ wk,
    const float* __restrict__ wv,
    float* __restrict__ q, float* __restrict__ k_, float* __restrict__ v)
{
    __shared__ float xs[HID];
    __shared__ float ws[3][32][33];
    const int row = blockIdx.x, tid = threadIdx.x;
    for (int t = tid; t < HID; t += 256) xs[t] = xln[(size_t)row * HID + t];
    for (int t = tid; t < 1024; t += 256) {
        const int e = t >> 5, d = t & 31;
        ws[0][e][d] = wq[t];
        ws[1][e][d] = wk[t];
        ws[2][e][d] = wv[t];
    }
    __syncthreads();
    for (int t = tid; t < 3 * HID; t += 256) {
        const int m = t / HID, r = t % HID;
        const int hh = r >> 5, e = r & 31;
        const float* xp = xs + (hh << 5);
        const float* wp = &ws[m][e][0];
        float s = 0.f;
        #pragma unroll
        for (int d = 0; d < 32; d++) s = fmaf(xp[d], wp[d], s);
        float* out = (m == 0) ? q : ((m == 1) ? k_ : v);
        out[(size_t)row * HID + r] = tf32r(s);
    }
}

// -------------------------------------------------- tensor-core attention
// One block per (n, h). 4 warps; warp w owns m16 q-tiles w, w+4, w+8, w+12.
// S = Q K^T (tf32 mma, keys padded to 208, masked), softmax in registers,
// P staged per-warp in smem, O = P V via second mma with V^T in smem.
#define ATS 36    // qs/ks row stride (floats)
#define PTS 212   // P / vT row stride (floats)

__global__ __launch_bounds__(128) void attn_tc_kernel(
    const float* __restrict__ q, const float* __restrict__ k,
    const float* __restrict__ v, const float* __restrict__ bias_mat,
    float* __restrict__ o)
{
    extern __shared__ float sm[];
    float* qs = sm;                       // LPAD*ATS   = 7488
    float* ks = qs + LPAD * ATS;          // LPAD*ATS   = 7488
    float* vT = ks + LPAD * ATS;          // 32*PTS     = 6784
    float* ps = vT + 32 * PTS;            // 4*16*PTS   = 13568

    const int nb = blockIdx.x;
    const int n = nb / NH, h = nb % NH;
    const int tid = threadIdx.x, lane = tid & 31, warp = tid >> 5;
    const size_t base = (size_t)n * LL * HID + (size_t)h * HD;

    // ---- stage Q, K (row-major, padded) and V^T into smem
    for (int t = tid; t < LL * HD; t += 128) {
        const int l = t >> 5, d = t & 31;
        const size_t g = base + (size_t)l * HID + d;
        qs[l * ATS + d] = q[g];
        ks[l * ATS + d] = k[g];
        vT[d * PTS + l] = v[g];
    }
    // zero pads: Q rows 196..207, V^T key-cols 196..207
    for (int t = tid; t < 12 * 32; t += 128)
        qs[(LL + (t >> 5)) * ATS + (t & 31)] = 0.f;
    for (int t = tid; t < 32 * 12; t += 128)
        vT[(t / 12) * PTS + LL + (t % 12)] = 0.f;
    __syncthreads();

    const float scale = 0.17677669529663687f;   // 1/sqrt(32)
    const int r = lane >> 2, jq = lane & 3;
    float* pw = ps + warp * 16 * PTS;

    for (int mt = warp; mt < 13; mt += 4) {
        const int row0 = mt * 16 + r;           // rows row0, row0+8

        // ---- S = Q K^T  (26 n-tiles over keys, 4 k-tiles over dims)
        float sacc[26][4];
        #pragma unroll
        for (int nt = 0; nt < 26; nt++)
            #pragma unroll
            for (int e = 0; e < 4; e++) sacc[nt][e] = 0.f;

        #pragma unroll
        for (int kt = 0; kt < 4; kt++) {
            const int kb = kt * 8 + jq;
            const uint32_t a0 = __float_as_uint(qs[row0 * ATS + kb]);
            const uint32_t a1 = __float_as_uint(qs[(row0 + 8) * ATS + kb]);
            const uint32_t a2 = __float_as_uint(qs[row0 * ATS + kb + 4]);
            const uint32_t a3 = __float_as_uint(qs[(row0 + 8) * ATS + kb + 4]);
            #pragma unroll
            for (int nt = 0; nt < 26; nt++) {
                const int kr = (nt * 8 + r) * ATS + kb;
                const uint32_t b0 = __float_as_uint(ks[kr]);
                const uint32_t b1 = __float_as_uint(ks[kr + 4]);
                mma_tf32(sacc[nt], a0, a1, a2, a3, b0, b1);
            }
        }

        // ---- bias + scale + masked row-max
        float mx0 = -1e30f, mx1 = -1e30f;
        #pragma unroll
        for (int nt = 0; nt < 26; nt++) {
            #pragma unroll
            for (int idx = 0; idx < 4; idx++) {
                const int e = idx & 1, half = idx >> 1;
                const int col = nt * 8 + 2 * jq + e;
                const int row = row0 + half * 8;
                float s;
                if (col < LL) {
                    s = (sacc[nt][idx] + bias_mat[row * LPAD + col]) * scale;
                } else {
                    s = -1e30f;
                }
                sacc[nt][idx] = s;
                if (half == 0) mx0 = fmaxf(mx0, s); else mx1 = fmaxf(mx1, s);
            }
        }
        mx0 = fmaxf(mx0, __shfl_xor_sync(0xffffffffu, mx0, 1));
        mx0 = fmaxf(mx0, __shfl_xor_sync(0xffffffffu, mx0, 2));
        mx1 = fmaxf(mx1, __shfl_xor_sync(0xffffffffu, mx1, 1));
        mx1 = fmaxf(mx1, __shfl_xor_sync(0xffffffffu, mx1, 2));

        // ---- exp + row-sum, write P (tf32-rounded) to per-warp smem
        float sum0 = 0.f, sum1 = 0.f;
        #pragma unroll
        for (int nt = 0; nt < 26; nt++) {
            #pragma unroll
            for (int idx = 0; idx < 4; idx++) {
                const int e = idx & 1, half = idx >> 1;
                const int col = nt * 8 + 2 * jq + e;
                float p = 0.f;
                if (col < LL) {
                    p = __expf(sacc[nt][idx] - (half ? mx1 : mx0));
                    if (half == 0) sum0 += p; else sum1 += p;
                }
                pw[(r + half * 8) * PTS + col] = tf32r(p);
            }
        }
        sum0 += __shfl_xor_sync(0xffffffffu, sum0, 1);
        sum0 += __shfl_xor_sync(0xffffffffu, sum0, 2);
        sum1 += __shfl_xor_sync(0xffffffffu, sum1, 1);
        sum1 += __shfl_xor_sync(0xffffffffu, sum1, 2);
        const float inv0 = 1.0f / sum0, inv1 = 1.0f / sum1;
        __syncwarp();

        // ---- O = P V   (M=16, N=32, K=208)
        float oacc[4][4];
        #pragma unroll
        for (int nt = 0; nt < 4; nt++)
            #pragma unroll
            for (int e = 0; e < 4; e++) oacc[nt][e] = 0.f;

        #pragma unroll
        for (int kt = 0; kt < 26; kt++) {
            const int kb = kt * 8 + jq;
            const uint32_t a0 = __float_as_uint(pw[r * PTS + kb]);
            const uint32_t a1 = __float_as_uint(pw[(r + 8) * PTS + kb]);
            const uint32_t a2 = __float_as_uint(pw[r * PTS + kb + 4]);
            const uint32_t a3 = __float_as_uint(pw[(r + 8) * PTS + kb + 4]);
            #pragma unroll
            for (int nt = 0; nt < 4; nt++) {
                const int vr = (nt * 8 + r) * PTS + kb;
                const uint32_t b0 = __float_as_uint(vT[vr]);
                const uint32_t b1 = __float_as_uint(vT[vr + 4]);
                mma_tf32(oacc[nt], a0, a1, a2, a3, b0, b1);
            }
        }

        // ---- store O (tf32-rounded, feeds w_out GEMM)
        #pragma unroll
        for (int nt = 0; nt < 4; nt++) {
            #pragma unroll
            for (int idx = 0; idx < 4; idx++) {
                const int e = idx & 1, half = idx >> 1;
                const int row = row0 + half * 8;
                const int col = nt * 8 + 2 * jq + e;
                if (row < LL) {
                    const float vv = oacc[nt][idx] * (half ? inv1 : inv0);
                    o[base + (size_t)row * HID + col] = tf32r(vv);
                }
            }
        }
        __syncwarp();
    }
}

// ------------------------------------------------------------ tf32 TC GEMM
// C[M,N] = A[M,K] @ B[N,K]^T (+bias); A,B pre-rounded to tf32 (raw-bit loads).
//   mode 0: plain   1: exact gelu (out rounded)   2: (resid + val) * rate
#define TBM 128
#define TBN 128
#define TBK 32
#define TSTRIDE 36

#define CP_ASYNC16(dst, src) \
    asm volatile("cp.async.cg.shared.global [%0], [%1], 16;\n" :: "r"(dst), "l"(src))

__global__ __launch_bounds__(128) void gemm_tc_kernel(
    const float* __restrict__ A, const float* __restrict__ B,
    const float* __restrict__ bias, const float* __restrict__ resid,
    float* __restrict__ C, int M, int N, int K, int mode, float rate)
{
    extern __shared__ float smg[];
    const int stageFloats = 2 * TBM * TSTRIDE;    // 9216

    const int tid  = threadIdx.x;
    const int lane = tid & 31, warp = tid >> 5;
    const int wr = warp >> 1, wc = warp & 1;
    const int bm = blockIdx.y * TBM, bn = blockIdx.x * TBN;

    const uint32_t smem_base = (uint32_t)__cvta_generic_to_shared(smg);
    const int nTiles = K / TBK;

    auto load_tile = [&](int kt, int s) {
        const float* Ag = A + (size_t)bm * K + (size_t)kt * TBK;
        const float* Bg = B + (size_t)bn * K + (size_t)kt * TBK;
        const uint32_t sA = smem_base + (uint32_t)(s * stageFloats) * 4u;
        const uint32_t sB = sA + (uint32_t)(TBM * TSTRIDE) * 4u;
        #pragma unroll
        for (int i = 0; i < 8; i++) {
            const int idx = i * 128 + tid;
            const int r = idx >> 3, c = idx & 7;
            CP_ASYNC16(sA + (uint32_t)(r * TSTRIDE * 4 + c * 16), Ag + (size_t)r * K + c * 4);
            CP_ASYNC16(sB + (uint32_t)(r * TSTRIDE * 4 + c * 16), Bg + (size_t)r * K + c * 4);
        }
    };

    float acc[4][8][4];
    #pragma unroll
    for (int i = 0; i < 4; i++)
        #pragma unroll
        for (int j = 0; j < 8; j++)
            #pragma unroll
            for (int r = 0; r < 4; r++) acc[i][j][r] = 0.f;

    const int aRow0 = wr * 64 + (lane >> 2);
    const int bRow0 = wc * 64 + (lane >> 2);
    const int kq = lane & 3;

    load_tile(0, 0);
    asm volatile("cp.async.commit_group;\n");

    for (int t = 0; t < nTiles; t++) {
        if (t + 1 < nTiles) {
            load_tile(t + 1, (t + 1) & 1);
            asm volatile("cp.async.commit_group;\n");
            asm volatile("cp.async.wait_group 1;\n");
        } else {
            asm volatile("cp.async.wait_group 0;\n");
        }
        __syncthreads();

        const uint32_t* As = (const uint32_t*)(smg + (t & 1) * stageFloats);
        const uint32_t* Bs = As + TBM * TSTRIDE;

        #pragma unroll
        for (int ks = 0; ks < 4; ks++) {
            const int kb = ks * 8 + kq;
            uint32_t bf[8][2];
            #pragma unroll
            for (int nt = 0; nt < 8; nt++) {
                const int rb = (bRow0 + nt * 8) * TSTRIDE + kb;
                bf[nt][0] = Bs[rb];
                bf[nt][1] = Bs[rb + 4];
            }
            #pragma unroll
            for (int mt = 0; mt < 4; mt++) {
                const int r0 = (aRow0 + mt * 16) * TSTRIDE + kb;
                const int r1 = r0 + 8 * TSTRIDE;
                const uint32_t a0 = As[r0];
                const uint32_t a1 = As[r1];
                const uint32_t a2 = As[r0 + 4];
                const uint32_t a3 = As[r1 + 4];
                #pragma unroll
                for (int nt = 0; nt < 8; nt++)
                    mma_tf32(acc[mt][nt], a0, a1, a2, a3, bf[nt][0], bf[nt][1]);
            }
        }
        __syncthreads();
    }

    // ------------------------------------------------------------- epilogue
    const int cRow0 = bm + wr * 64 + (lane >> 2);
    const int cCol0 = bn + wc * 64 + 2 * (lane & 3);
    #pragma unroll
    for (int mt = 0; mt < 4; mt++) {
        #pragma unroll
        for (int nt = 0; nt < 8; nt++) {
            #pragma unroll
            for (int half = 0; half < 2; half++) {
                const int row = cRow0 + mt * 16 + half * 8;
                #pragma unroll
                for (int e = 0; e < 2; e++) {
                    const int col = cCol0 + nt * 8 + e;
                    float vv = acc[mt][nt][half * 2 + e];
                    if (bias) vv += bias[col];
                    if (mode == 1) {
                        vv = 0.5f * vv * (1.0f + erff(vv * 0.70710678118654752f));
                        vv = tf32r(vv);      // feeds ffn2 A
                    } else if (mode == 2) {
                        vv = (resid[(size_t)row * N + col] + vv) * rate;
                    }
                    C[(size_t)row * N + col] = vv;
                }
            }
        }
    }
}

// --------------------------------------------------------------------- host
extern "C" void kernel_launch(void* const* d_in, const int* in_sizes, int n_in,
                              void* d_out, int out_size)
{
    const float* x        = (const float*)d_in[0];
    const float* rel_bias = (const float*)d_in[1];
    const float* wq       = (const float*)d_in[2];
    const float* wk       = (const float*)d_in[3];
    const float* wv       = (const float*)d_in[4];
    const float* w_out    = (const float*)d_in[5];
    const float* ln1_g    = (const float*)d_in[6];
    const float* ln1_b    = (const float*)d_in[7];
    const float* ln2_g    = (const float*)d_in[8];
    const float* ln2_b    = (const float*)d_in[9];
    const float* w1       = (const float*)d_in[10];
    const float* b1       = (const float*)d_in[11];
    const float* w2       = (const float*)d_in[12];
    const float* b2       = (const float*)d_in[13];
    float* out = (float*)d_out;

    float *p_ln, *p_q, *p_k, *p_v, *p_o, *p_h;
    float *p_wor, *p_w1r, *p_w2r, *p_bias;
    cudaGetSymbolAddress((void**)&p_ln, g_ln);
    cudaGetSymbolAddress((void**)&p_q,  g_q);
    cudaGetSymbolAddress((void**)&p_k,  g_k);
    cudaGetSymbolAddress((void**)&p_v,  g_v);
    cudaGetSymbolAddress((void**)&p_o,  g_o);
    cudaGetSymbolAddress((void**)&p_h,  g_h);
    cudaGetSymbolAddress((void**)&p_wor, g_wout_r);
    cudaGetSymbolAddress((void**)&p_w1r, g_w1_r);
    cudaGetSymbolAddress((void**)&p_w2r, g_w2_r);
    cudaGetSymbolAddress((void**)&p_bias, g_bias);

    const int attn_smem = (2 * LPAD * ATS + 32 * PTS + 4 * 16 * PTS) * (int)sizeof(float);
    cudaFuncSetAttribute(attn_tc_kernel,
                         cudaFuncAttributeMaxDynamicSharedMemorySize, attn_smem);
    const int gemm_smem = 2 * 2 * TBM * TSTRIDE * (int)sizeof(float);  // 73728
    cudaFuncSetAttribute(gemm_tc_kernel,
                         cudaFuncAttributeMaxDynamicSharedMemorySize, gemm_smem);

    // 0) one-time-per-replay prep (cheap): round weights, build bias matrix
    round_w_kernel<<<(HID * HID + 255) / 256, 256>>>(w_out, p_wor, HID * HID);
    round_w_kernel<<<(FF * HID + 255) / 256, 256>>>(w1, p_w1r, FF * HID);
    round_w_kernel<<<(HID * FF + 255) / 256, 256>>>(w2, p_w2r, HID * FF);
    bias_init_kernel<<<(LPAD * LPAD + 255) / 256, 256>>>(rel_bias, p_bias);

    // 1) ln1 (tf32-rounded output)
    ln_kernel<<<M_ROWS, 256>>>(x, ln1_g, ln1_b, p_ln);
    // 2) q/k/v head projections (tf32-rounded)
    qkv_kernel<<<M_ROWS, 256>>>(p_ln, wq, wk, wv, p_q, p_k, p_v);
    // 3) tensor-core attention
    attn_tc_kernel<<<NB * NH, 128, attn_smem>>>(p_q, p_k, p_v, p_bias, p_o);
    // 4) output projection + residual + rate -> d_out holds x1
    {
        dim3 grid(HID / TBN, M_ROWS / TBM);
        gemm_tc_kernel<<<grid, 128, gemm_smem>>>(p_o, p_wor, nullptr, x, out,
                                                 M_ROWS, HID, HID, 2, RATE_F);
    }
    // 5) ln2
    ln_kernel<<<M_ROWS, 256>>>(out, ln2_g, ln2_b, p_ln);
    // 6) ffn1 + gelu (rounded output)
    {
        dim3 grid(FF / TBN, M_ROWS / TBM);
        gemm_tc_kernel<<<grid, 128, gemm_smem>>>(p_ln, p_w1r, b1, nullptr, p_h,
                                                 M_ROWS, FF, HID, 1, 0.f);
    }
    // 7) ffn2 + residual + rate -> d_out final
    {
        dim3 grid(HID / TBN, M_ROWS / TBM);
        gemm_tc_kernel<<<grid, 128, gemm_smem>>>(p_h, p_w2r, b2, out, out,
                                                 M_ROWS, HID, FF, 2, RATE_F);
    }
}

// round 6
// speedup vs baseline: 3.4104x; 1.1524x over previous
#include <cuda_runtime.h>
#include <cuda_bf16.h>
#include <math.h>
#include <stdint.h>

// Problem constants
#define NB     64
#define LL     196
#define HID    768
#define FF     3072
#define NH     24
#define HD     32
#define M_ROWS (NB * LL)          // 12544
#define RATE_F 0.2f
#define LPAD   208                // 196 padded to 13*16 (and 26*8)

// ---------------- scratch (static device globals; no runtime allocation) ----
__device__ float g_ln[(size_t)M_ROWS * HID];
__device__ float g_q [(size_t)M_ROWS * HID];
__device__ float g_k [(size_t)M_ROWS * HID];
__device__ float g_v [(size_t)M_ROWS * HID];
__device__ float g_o [(size_t)M_ROWS * HID];
__device__ float g_h [(size_t)M_ROWS * FF];
__device__ float g_wout_r[HID * HID];
__device__ float g_w1_r[FF * HID];
__device__ float g_w2_r[HID * FF];
__device__ float g_bias[LPAD * LPAD];

// ------------------------------------------------------------ tf32 helpers
__device__ __forceinline__ uint32_t f2tf(float f) {
    uint32_t r;
    asm("cvt.rna.tf32.f32 %0, %1;" : "=r"(r) : "f"(f));
    return r;
}
__device__ __forceinline__ float tf32r(float f) {
    return __uint_as_float(f2tf(f));
}
__device__ __forceinline__ void mma_tf32(
    float* c, uint32_t a0, uint32_t a1, uint32_t a2, uint32_t a3,
    uint32_t b0, uint32_t b1)
{
    asm volatile(
        "mma.sync.aligned.m16n8k8.row.col.f32.tf32.tf32.f32 "
        "{%0,%1,%2,%3}, {%4,%5,%6,%7}, {%8,%9}, {%0,%1,%2,%3};\n"
        : "+f"(c[0]), "+f"(c[1]), "+f"(c[2]), "+f"(c[3])
        : "r"(a0), "r"(a1), "r"(a2), "r"(a3), "r"(b0), "r"(b1));
}

// ----------------------------------------------------- weight pre-rounding
__global__ __launch_bounds__(256) void round_w_kernel(
    const float* __restrict__ w, float* __restrict__ out, int n)
{
    int i = blockIdx.x * 256 + threadIdx.x;
    if (i < n) out[i] = tf32r(w[i]);
}

// ----------------------------------------------------- bias matrix builder
__global__ __launch_bounds__(256) void bias_init_kernel(
    const float* __restrict__ rel_bias, float* __restrict__ bm)
{
    int idx = blockIdx.x * 256 + threadIdx.x;
    if (idx >= LPAD * LPAD) return;
    int row = idx / LPAD, col = idx % LPAD;
    float val = 0.f;
    if (row < LL && col < LL) {
        int qi = row / 14, qj = row % 14;
        int ki = col / 14, kj = col % 14;
        val = rel_bias[(qi - ki + 14) * 28 + (qj - kj + 14)];
    }
    bm[idx] = val;
}

// ---------------------------------------------------------------- LayerNorm
__global__ __launch_bounds__(256) void ln_kernel(
    const float* __restrict__ x, const float* __restrict__ g,
    const float* __restrict__ b, float* __restrict__ y)
{
    __shared__ float sm8[8];
    __shared__ float sstat;
    const int row = blockIdx.x, tid = threadIdx.x;
    const float* xr = x + (size_t)row * HID;
    float v0 = xr[tid], v1 = xr[tid + 256], v2 = xr[tid + 512];
    float s = v0 + v1 + v2;
    #pragma unroll
    for (int off = 16; off; off >>= 1) s += __shfl_xor_sync(0xffffffffu, s, off);
    if ((tid & 31) == 0) sm8[tid >> 5] = s;
    __syncthreads();
    if (tid == 0) {
        float t = 0.f;
        #pragma unroll
        for (int i = 0; i < 8; i++) t += sm8[i];
        sstat = t * (1.0f / HID);
    }
    __syncthreads();
    const float mu = sstat;
    float d0 = v0 - mu, d1 = v1 - mu, d2 = v2 - mu;
    float q = d0 * d0 + d1 * d1 + d2 * d2;
    #pragma unroll
    for (int off = 16; off; off >>= 1) q += __shfl_xor_sync(0xffffffffu, q, off);
    __syncthreads();
    if ((tid & 31) == 0) sm8[tid >> 5] = q;
    __syncthreads();
    if (tid == 0) {
        float t = 0.f;
        #pragma unroll
        for (int i = 0; i < 8; i++) t += sm8[i];
        sstat = rsqrtf(t * (1.0f / HID) + 1e-5f);
    }
    __syncthreads();
    const float r = sstat;
    float* yr = y + (size_t)row * HID;
    yr[tid]       = tf32r(d0 * r * g[tid]       + b[tid]);
    yr[tid + 256] = tf32r(d1 * r * g[tid + 256] + b[tid + 256]);
    yr[tid + 512] = tf32r(d2 * r * g[tid + 512] + b[tid + 512]);
}

// ------------------------------------------ fused LayerNorm1 + QKV projection
__global__ __launch_bounds__(256) void ln_qkv_kernel(
    const float* __restrict__ x, const float* __restrict__ g,
    const float* __restrict__ b,
    const float* __restrict__ wq, const float* __restrict__ wk,
    const float* __restrict__ wv,
    float* __restrict__ q, float* __restrict__ k_, float* __restrict__ v)
{
    __shared__ float xs[HID];
    __shared__ float ws[3][32][33];
    __shared__ float sm8[8];
    __shared__ float sstat;
    const int row = blockIdx.x, tid = threadIdx.x;

    // weights (independent of LN)
    for (int t = tid; t < 1024; t += 256) {
        const int e = t >> 5, d = t & 31;
        ws[0][e][d] = wq[t];
        ws[1][e][d] = wk[t];
        ws[2][e][d] = wv[t];
    }

    const float* xr = x + (size_t)row * HID;
    float v0 = xr[tid], v1 = xr[tid + 256], v2 = xr[tid + 512];
    float s = v0 + v1 + v2;
    #pragma unroll
    for (int off = 16; off; off >>= 1) s += __shfl_xor_sync(0xffffffffu, s, off);
    if ((tid & 31) == 0) sm8[tid >> 5] = s;
    __syncthreads();
    if (tid == 0) {
        float t = 0.f;
        #pragma unroll
        for (int i = 0; i < 8; i++) t += sm8[i];
        sstat = t * (1.0f / HID);
    }
    __syncthreads();
    const float mu = sstat;
    float d0 = v0 - mu, d1 = v1 - mu, d2 = v2 - mu;
    float qq = d0 * d0 + d1 * d1 + d2 * d2;
    #pragma unroll
    for (int off = 16; off; off >>= 1) qq += __shfl_xor_sync(0xffffffffu, qq, off);
    __syncthreads();
    if ((tid & 31) == 0) sm8[tid >> 5] = qq;
    __syncthreads();
    if (tid == 0) {
        float t = 0.f;
        #pragma unroll
        for (int i = 0; i < 8; i++) t += sm8[i];
        sstat = rsqrtf(t * (1.0f / HID) + 1e-5f);
    }
    __syncthreads();
    const float r = sstat;
    xs[tid]       = d0 * r * g[tid]       + b[tid];
    xs[tid + 256] = d1 * r * g[tid + 256] + b[tid + 256];
    xs[tid + 512] = d2 * r * g[tid + 512] + b[tid + 512];
    __syncthreads();

    for (int t = tid; t < 3 * HID; t += 256) {
        const int m = t / HID, rr = t % HID;
        const int hh = rr >> 5, e = rr & 31;
        const float* xp = xs + (hh << 5);
        const float* wp = &ws[m][e][0];
        float acc = 0.f;
        #pragma unroll
        for (int d = 0; d < 32; d++) acc = fmaf(xp[d], wp[d], acc);
        float* out = (m == 0) ? q : ((m == 1) ? k_ : v);
        out[(size_t)row * HID + rr] = tf32r(acc);
    }
}

// -------------------------------------------------- tensor-core attention
// One block per (n, h), 128 threads (4 warps), 2 blocks/SM (87 KB smem).
// S = Q K^T (tf32 mma, keys padded to 208, masked); softmax in registers;
// P converted to PV A-fragments via warp shuffles (no smem round-trip);
// O = P V with V^T in smem.
#define ATS 36    // qs/ks row stride (floats)
#define VTS 212   // vT row stride (floats)

__global__ __launch_bounds__(128, 2) void attn_tc_kernel(
    const float* __restrict__ q, const float* __restrict__ k,
    const float* __restrict__ v, const float* __restrict__ bias_mat,
    float* __restrict__ o)
{
    extern __shared__ float sm[];
    float* qs = sm;                       // LPAD*ATS = 7488
    float* ks = qs + LPAD * ATS;          // LPAD*ATS = 7488
    float* vT = ks + LPAD * ATS;          // 32*VTS   = 6784

    const int nb = blockIdx.x;
    const int n = nb / NH, h = nb % NH;
    const int tid = threadIdx.x, lane = tid & 31, warp = tid >> 5;
    const size_t base = (size_t)n * LL * HID + (size_t)h * HD;

    // ---- stage Q, K (row-major, padded) and V^T into smem
    for (int t = tid; t < LL * HD; t += 128) {
        const int l = t >> 5, d = t & 31;
        const size_t g = base + (size_t)l * HID + d;
        qs[l * ATS + d] = q[g];
        ks[l * ATS + d] = k[g];
        vT[d * VTS + l] = v[g];
    }
    // zero pads: Q rows 196..207, V^T key-cols 196..207
    for (int t = tid; t < 12 * 32; t += 128)
        qs[(LL + (t >> 5)) * ATS + (t & 31)] = 0.f;
    for (int t = tid; t < 32 * 12; t += 128)
        vT[(t / 12) * VTS + LL + (t % 12)] = 0.f;
    __syncthreads();

    const float scale = 0.17677669529663687f;   // 1/sqrt(32)
    const int r = lane >> 2, jq = lane & 3;
    const int srcA = (lane & ~3) | (jq >> 1);
    const int srcB = srcA + 2;
    const bool odd = (jq & 1) != 0;

    for (int mt = warp; mt < 13; mt += 4) {
        const int row0 = mt * 16 + r;           // rows row0, row0+8

        // ---- S = Q K^T  (26 n-tiles over keys, 4 k-tiles over dims)
        float sacc[26][4];
        #pragma unroll
        for (int nt = 0; nt < 26; nt++)
            #pragma unroll
            for (int e = 0; e < 4; e++) sacc[nt][e] = 0.f;

        #pragma unroll
        for (int kt = 0; kt < 4; kt++) {
            const int kb = kt * 8 + jq;
            const uint32_t a0 = __float_as_uint(qs[row0 * ATS + kb]);
            const uint32_t a1 = __float_as_uint(qs[(row0 + 8) * ATS + kb]);
            const uint32_t a2 = __float_as_uint(qs[row0 * ATS + kb + 4]);
            const uint32_t a3 = __float_as_uint(qs[(row0 + 8) * ATS + kb + 4]);
            #pragma unroll
            for (int nt = 0; nt < 26; nt++) {
                const int kr = (nt * 8 + r) * ATS + kb;
                const uint32_t b0 = __float_as_uint(ks[kr]);
                const uint32_t b1 = __float_as_uint(ks[kr + 4]);
                mma_tf32(sacc[nt], a0, a1, a2, a3, b0, b1);
            }
        }

        // ---- bias + scale + masked row-max
        float mx0 = -1e30f, mx1 = -1e30f;
        #pragma unroll
        for (int nt = 0; nt < 26; nt++) {
            #pragma unroll
            for (int idx = 0; idx < 4; idx++) {
                const int e = idx & 1, half = idx >> 1;
                const int col = nt * 8 + 2 * jq + e;
                const int row = row0 + half * 8;
                float s;
                if (col < LL) {
                    s = (sacc[nt][idx] + bias_mat[row * LPAD + col]) * scale;
                } else {
                    s = -1e30f;
                }
                sacc[nt][idx] = s;
                if (half == 0) mx0 = fmaxf(mx0, s); else mx1 = fmaxf(mx1, s);
            }
        }
        mx0 = fmaxf(mx0, __shfl_xor_sync(0xffffffffu, mx0, 1));
        mx0 = fmaxf(mx0, __shfl_xor_sync(0xffffffffu, mx0, 2));
        mx1 = fmaxf(mx1, __shfl_xor_sync(0xffffffffu, mx1, 1));
        mx1 = fmaxf(mx1, __shfl_xor_sync(0xffffffffu, mx1, 2));

        // ---- exp in registers (unnormalized P; zero at pad cols)
        float sum0 = 0.f, sum1 = 0.f;
        #pragma unroll
        for (int nt = 0; nt < 26; nt++) {
            #pragma unroll
            for (int idx = 0; idx < 4; idx++) {
                const int e = idx & 1, half = idx >> 1;
                const int col = nt * 8 + 2 * jq + e;
                float p = 0.f;
                if (col < LL) {
                    p = __expf(sacc[nt][idx] - (half ? mx1 : mx0));
                    if (half == 0) sum0 += p; else sum1 += p;
                }
                sacc[nt][idx] = p;
            }
        }
        sum0 += __shfl_xor_sync(0xffffffffu, sum0, 1);
        sum0 += __shfl_xor_sync(0xffffffffu, sum0, 2);
        sum1 += __shfl_xor_sync(0xffffffffu, sum1, 1);
        sum1 += __shfl_xor_sync(0xffffffffu, sum1, 2);
        const float inv0 = 1.0f / sum0, inv1 = 1.0f / sum1;

        // ---- O = P V  (M=16, N=32, K=208); A-frags built via shuffles
        float oacc[4][4];
        #pragma unroll
        for (int nt = 0; nt < 4; nt++)
            #pragma unroll
            for (int e = 0; e < 4; e++) oacc[nt][e] = 0.f;

        #pragma unroll
        for (int kt = 0; kt < 26; kt++) {
            const float x0 = __shfl_sync(0xffffffffu, sacc[kt][0], srcA);
            const float x1 = __shfl_sync(0xffffffffu, sacc[kt][1], srcA);
            const float x2 = __shfl_sync(0xffffffffu, sacc[kt][2], srcA);
            const float x3 = __shfl_sync(0xffffffffu, sacc[kt][3], srcA);
            const float y0 = __shfl_sync(0xffffffffu, sacc[kt][0], srcB);
            const float y1 = __shfl_sync(0xffffffffu, sacc[kt][1], srcB);
            const float y2 = __shfl_sync(0xffffffffu, sacc[kt][2], srcB);
            const float y3 = __shfl_sync(0xffffffffu, sacc[kt][3], srcB);
            const uint32_t a0 = __float_as_uint(odd ? x1 : x0);
            const uint32_t a1 = __float_as_uint(odd ? x3 : x2);
            const uint32_t a2 = __float_as_uint(odd ? y1 : y0);
            const uint32_t a3 = __float_as_uint(odd ? y3 : y2);
            const int kb = kt * 8 + jq;
            #pragma unroll
            for (int nt = 0; nt < 4; nt++) {
                const int vr = (nt * 8 + r) * VTS + kb;
                const uint32_t b0 = __float_as_uint(vT[vr]);
                const uint32_t b1 = __float_as_uint(vT[vr + 4]);
                mma_tf32(oacc[nt], a0, a1, a2, a3, b0, b1);
            }
        }

        // ---- store O (tf32-rounded, feeds w_out GEMM)
        #pragma unroll
        for (int nt = 0; nt < 4; nt++) {
            #pragma unroll
            for (int idx = 0; idx < 4; idx++) {
                const int e = idx & 1, half = idx >> 1;
                const int row = row0 + half * 8;
                const int col = nt * 8 + 2 * jq + e;
                if (row < LL) {
                    const float vv = oacc[nt][idx] * (half ? inv1 : inv0);
                    o[base + (size_t)row * HID + col] = tf32r(vv);
                }
            }
        }
    }
}

// ------------------------------------------------------------ tf32 TC GEMM
// C[M,N] = A[M,K] @ B[N,K]^T (+bias); A,B pre-rounded to tf32 (raw-bit loads).
//   mode 0: plain   1: exact gelu (out rounded)   2: (resid + val) * rate
#define TBM 128
#define TBN 128
#define TBK 32
#define TSTRIDE 36

#define CP_ASYNC16(dst, src) \
    asm volatile("cp.async.cg.shared.global [%0], [%1], 16;\n" :: "r"(dst), "l"(src))

__global__ __launch_bounds__(128) void gemm_tc_kernel(
    const float* __restrict__ A, const float* __restrict__ B,
    const float* __restrict__ bias, const float* __restrict__ resid,
    float* __restrict__ C, int M, int N, int K, int mode, float rate)
{
    extern __shared__ float smg[];
    const int stageFloats = 2 * TBM * TSTRIDE;    // 9216

    const int tid  = threadIdx.x;
    const int lane = tid & 31, warp = tid >> 5;
    const int wr = warp >> 1, wc = warp & 1;
    const int bm = blockIdx.y * TBM, bn = blockIdx.x * TBN;

    const uint32_t smem_base = (uint32_t)__cvta_generic_to_shared(smg);
    const int nTiles = K / TBK;

    auto load_tile = [&](int kt, int s) {
        const float* Ag = A + (size_t)bm * K + (size_t)kt * TBK;
        const float* Bg = B + (size_t)bn * K + (size_t)kt * TBK;
        const uint32_t sA = smem_base + (uint32_t)(s * stageFloats) * 4u;
        const uint32_t sB = sA + (uint32_t)(TBM * TSTRIDE) * 4u;
        #pragma unroll
        for (int i = 0; i < 8; i++) {
            const int idx = i * 128 + tid;
            const int r = idx >> 3, c = idx & 7;
            CP_ASYNC16(sA + (uint32_t)(r * TSTRIDE * 4 + c * 16), Ag + (size_t)r * K + c * 4);
            CP_ASYNC16(sB + (uint32_t)(r * TSTRIDE * 4 + c * 16), Bg + (size_t)r * K + c * 4);
        }
    };

    float acc[4][8][4];
    #pragma unroll
    for (int i = 0; i < 4; i++)
        #pragma unroll
        for (int j = 0; j < 8; j++)
            #pragma unroll
            for (int r = 0; r < 4; r++) acc[i][j][r] = 0.f;

    const int aRow0 = wr * 64 + (lane >> 2);
    const int bRow0 = wc * 64 + (lane >> 2);
    const int kq = lane & 3;

    load_tile(0, 0);
    asm volatile("cp.async.commit_group;\n");

    for (int t = 0; t < nTiles; t++) {
        if (t + 1 < nTiles) {
            load_tile(t + 1, (t + 1) & 1);
            asm volatile("cp.async.commit_group;\n");
            asm volatile("cp.async.wait_group 1;\n");
        } else {
            asm volatile("cp.async.wait_group 0;\n");
        }
        __syncthreads();

        const uint32_t* As = (const uint32_t*)(smg + (t & 1) * stageFloats);
        const uint32_t* Bs = As + TBM * TSTRIDE;

        #pragma unroll
        for (int ks = 0; ks < 4; ks++) {
            const int kb = ks * 8 + kq;
            uint32_t bf[8][2];
            #pragma unroll
            for (int nt = 0; nt < 8; nt++) {
                const int rb = (bRow0 + nt * 8) * TSTRIDE + kb;
                bf[nt][0] = Bs[rb];
                bf[nt][1] = Bs[rb + 4];
            }
            #pragma unroll
            for (int mt = 0; mt < 4; mt++) {
                const int r0 = (aRow0 + mt * 16) * TSTRIDE + kb;
                const int r1 = r0 + 8 * TSTRIDE;
                const uint32_t a0 = As[r0];
                const uint32_t a1 = As[r1];
                const uint32_t a2 = As[r0 + 4];
                const uint32_t a3 = As[r1 + 4];
                #pragma unroll
                for (int nt = 0; nt < 8; nt++)
                    mma_tf32(acc[mt][nt], a0, a1, a2, a3, bf[nt][0], bf[nt][1]);
            }
        }
        __syncthreads();
    }

    // ------------------------------------------------------------- epilogue
    const int cRow0 = bm + wr * 64 + (lane >> 2);
    const int cCol0 = bn + wc * 64 + 2 * (lane & 3);
    #pragma unroll
    for (int mt = 0; mt < 4; mt++) {
        #pragma unroll
        for (int nt = 0; nt < 8; nt++) {
            #pragma unroll
            for (int half = 0; half < 2; half++) {
                const int row = cRow0 + mt * 16 + half * 8;
                #pragma unroll
                for (int e = 0; e < 2; e++) {
                    const int col = cCol0 + nt * 8 + e;
                    float vv = acc[mt][nt][half * 2 + e];
                    if (bias) vv += bias[col];
                    if (mode == 1) {
                        vv = 0.5f * vv * (1.0f + erff(vv * 0.70710678118654752f));
                        vv = tf32r(vv);      // feeds ffn2 A
                    } else if (mode == 2) {
                        vv = (resid[(size_t)row * N + col] + vv) * rate;
                    }
                    C[(size_t)row * N + col] = vv;
                }
            }
        }
    }
}

// --------------------------------------------------------------------- host
extern "C" void kernel_launch(void* const* d_in, const int* in_sizes, int n_in,
                              void* d_out, int out_size)
{
    const float* x        = (const float*)d_in[0];
    const float* rel_bias = (const float*)d_in[1];
    const float* wq       = (const float*)d_in[2];
    const float* wk       = (const float*)d_in[3];
    const float* wv       = (const float*)d_in[4];
    const float* w_out    = (const float*)d_in[5];
    const float* ln1_g    = (const float*)d_in[6];
    const float* ln1_b    = (const float*)d_in[7];
    const float* ln2_g    = (const float*)d_in[8];
    const float* ln2_b    = (const float*)d_in[9];
    const float* w1       = (const float*)d_in[10];
    const float* b1       = (const float*)d_in[11];
    const float* w2       = (const float*)d_in[12];
    const float* b2       = (const float*)d_in[13];
    float* out = (float*)d_out;

    float *p_ln, *p_q, *p_k, *p_v, *p_o, *p_h;
    float *p_wor, *p_w1r, *p_w2r, *p_bias;
    cudaGetSymbolAddress((void**)&p_ln, g_ln);
    cudaGetSymbolAddress((void**)&p_q,  g_q);
    cudaGetSymbolAddress((void**)&p_k,  g_k);
    cudaGetSymbolAddress((void**)&p_v,  g_v);
    cudaGetSymbolAddress((void**)&p_o,  g_o);
    cudaGetSymbolAddress((void**)&p_h,  g_h);
    cudaGetSymbolAddress((void**)&p_wor, g_wout_r);
    cudaGetSymbolAddress((void**)&p_w1r, g_w1_r);
    cudaGetSymbolAddress((void**)&p_w2r, g_w2_r);
    cudaGetSymbolAddress((void**)&p_bias, g_bias);

    const int attn_smem = (2 * LPAD * ATS + 32 * VTS) * (int)sizeof(float);  // 87040
    cudaFuncSetAttribute(attn_tc_kernel,
                         cudaFuncAttributeMaxDynamicSharedMemorySize, attn_smem);
    const int gemm_smem = 2 * 2 * TBM * TSTRIDE * (int)sizeof(float);  // 73728
    cudaFuncSetAttribute(gemm_tc_kernel,
                         cudaFuncAttributeMaxDynamicSharedMemorySize, gemm_smem);

    // 0) prep: round weights, build bias matrix
    round_w_kernel<<<(HID * HID + 255) / 256, 256>>>(w_out, p_wor, HID * HID);
    round_w_kernel<<<(FF * HID + 255) / 256, 256>>>(w1, p_w1r, FF * HID);
    round_w_kernel<<<(HID * FF + 255) / 256, 256>>>(w2, p_w2r, HID * FF);
    bias_init_kernel<<<(LPAD * LPAD + 255) / 256, 256>>>(rel_bias, p_bias);

    // 1) fused ln1 + q/k/v projections
    ln_qkv_kernel<<<M_ROWS, 256>>>(x, ln1_g, ln1_b, wq, wk, wv, p_q, p_k, p_v);
    // 2) tensor-core attention
    attn_tc_kernel<<<NB * NH, 128, attn_smem>>>(p_q, p_k, p_v, p_bias, p_o);
    // 3) output projection + residual + rate -> d_out holds x1
    {
        dim3 grid(HID / TBN, M_ROWS / TBM);
        gemm_tc_kernel<<<grid, 128, gemm_smem>>>(p_o, p_wor, nullptr, x, out,
                                                 M_ROWS, HID, HID, 2, RATE_F);
    }
    // 4) ln2
    ln_kernel<<<M_ROWS, 256>>>(out, ln2_g, ln2_b, p_ln);
    // 5) ffn1 + gelu (rounded output)
    {
        dim3 grid(FF / TBN, M_ROWS / TBM);
        gemm_tc_kernel<<<grid, 128, gemm_smem>>>(p_ln, p_w1r, b1, nullptr, p_h,
                                                 M_ROWS, FF, HID, 1, 0.f);
    }
    // 6) ffn2 + residual + rate -> d_out final
    {
        dim3 grid(HID / TBN, M_ROWS / TBM);
        gemm_tc_kernel<<<grid, 128, gemm_smem>>>(p_h, p_w2r, b2, out, out,
                                                 M_ROWS, HID, FF, 2, RATE_F);
    }
}

// round 7
// speedup vs baseline: 3.4226x; 1.0036x over previous
#include <cuda_runtime.h>
#include <cuda_bf16.h>
#include <math.h>
#include <stdint.h>

// Problem constants
#define NB     64
#define LL     196
#define HID    768
#define FF     3072
#define NH     24
#define HD     32
#define M_ROWS (NB * LL)          // 12544
#define RATE_F 0.2f
#define LPAD   208                // 196 padded to 13*16 (and 26*8)

// ---------------- scratch (static device globals; no runtime allocation) ----
__device__ float g_ln[(size_t)M_ROWS * HID];
__device__ float g_q [(size_t)M_ROWS * HID];
__device__ float g_k [(size_t)M_ROWS * HID];
__device__ float g_v [(size_t)M_ROWS * HID];
__device__ float g_o [(size_t)M_ROWS * HID];
__device__ float g_h [(size_t)M_ROWS * FF];
__device__ float g_bias[LPAD * LPAD];

// ------------------------------------------------------------ tf32 helpers
__device__ __forceinline__ uint32_t f2tf(float f) {
    uint32_t r;
    asm("cvt.rna.tf32.f32 %0, %1;" : "=r"(r) : "f"(f));
    return r;
}
__device__ __forceinline__ float tf32r(float f) {
    return __uint_as_float(f2tf(f));
}
__device__ __forceinline__ void mma_tf32(
    float* c, uint32_t a0, uint32_t a1, uint32_t a2, uint32_t a3,
    uint32_t b0, uint32_t b1)
{
    asm volatile(
        "mma.sync.aligned.m16n8k8.row.col.f32.tf32.tf32.f32 "
        "{%0,%1,%2,%3}, {%4,%5,%6,%7}, {%8,%9}, {%0,%1,%2,%3};\n"
        : "+f"(c[0]), "+f"(c[1]), "+f"(c[2]), "+f"(c[3])
        : "r"(a0), "r"(a1), "r"(a2), "r"(a3), "r"(b0), "r"(b1));
}

// ----------------------------------------------------- bias matrix builder
__global__ __launch_bounds__(256) void bias_init_kernel(
    const float* __restrict__ rel_bias, float* __restrict__ bm)
{
    int idx = blockIdx.x * 256 + threadIdx.x;
    if (idx >= LPAD * LPAD) return;
    int row = idx / LPAD, col = idx % LPAD;
    float val = 0.f;
    if (row < LL && col < LL) {
        int qi = row / 14, qj = row % 14;
        int ki = col / 14, kj = col % 14;
        val = rel_bias[(qi - ki + 14) * 28 + (qj - kj + 14)];
    }
    bm[idx] = val;
}

// ---------------------------------------------------------------- LayerNorm
__global__ __launch_bounds__(256) void ln_kernel(
    const float* __restrict__ x, const float* __restrict__ g,
    const float* __restrict__ b, float* __restrict__ y)
{
    __shared__ float sm8[8];
    __shared__ float sstat;
    const int row = blockIdx.x, tid = threadIdx.x;
    const float* xr = x + (size_t)row * HID;
    float v0 = xr[tid], v1 = xr[tid + 256], v2 = xr[tid + 512];
    float s = v0 + v1 + v2;
    #pragma unroll
    for (int off = 16; off; off >>= 1) s += __shfl_xor_sync(0xffffffffu, s, off);
    if ((tid & 31) == 0) sm8[tid >> 5] = s;
    __syncthreads();
    if (tid == 0) {
        float t = 0.f;
        #pragma unroll
        for (int i = 0; i < 8; i++) t += sm8[i];
        sstat = t * (1.0f / HID);
    }
    __syncthreads();
    const float mu = sstat;
    float d0 = v0 - mu, d1 = v1 - mu, d2 = v2 - mu;
    float q = d0 * d0 + d1 * d1 + d2 * d2;
    #pragma unroll
    for (int off = 16; off; off >>= 1) q += __shfl_xor_sync(0xffffffffu, q, off);
    __syncthreads();
    if ((tid & 31) == 0) sm8[tid >> 5] = q;
    __syncthreads();
    if (tid == 0) {
        float t = 0.f;
        #pragma unroll
        for (int i = 0; i < 8; i++) t += sm8[i];
        sstat = rsqrtf(t * (1.0f / HID) + 1e-5f);
    }
    __syncthreads();
    const float r = sstat;
    float* yr = y + (size_t)row * HID;
    yr[tid]       = tf32r(d0 * r * g[tid]       + b[tid]);
    yr[tid + 256] = tf32r(d1 * r * g[tid + 256] + b[tid + 256]);
    yr[tid + 512] = tf32r(d2 * r * g[tid + 512] + b[tid + 512]);
}

// ------------------------------------------ fused LayerNorm1 + QKV projection
__global__ __launch_bounds__(256) void ln_qkv_kernel(
    const float* __restrict__ x, const float* __restrict__ g,
    const float* __restrict__ b,
    const float* __restrict__ wq, const float* __restrict__ wk,
    const float* __restrict__ wv,
    float* __restrict__ q, float* __restrict__ k_, float* __restrict__ v)
{
    __shared__ float xs[HID];
    __shared__ float ws[3][32][33];
    __shared__ float sm8[8];
    __shared__ float sstat;
    const int row = blockIdx.x, tid = threadIdx.x;

    for (int t = tid; t < 1024; t += 256) {
        const int e = t >> 5, d = t & 31;
        ws[0][e][d] = wq[t];
        ws[1][e][d] = wk[t];
        ws[2][e][d] = wv[t];
    }

    const float* xr = x + (size_t)row * HID;
    float v0 = xr[tid], v1 = xr[tid + 256], v2 = xr[tid + 512];
    float s = v0 + v1 + v2;
    #pragma unroll
    for (int off = 16; off; off >>= 1) s += __shfl_xor_sync(0xffffffffu, s, off);
    if ((tid & 31) == 0) sm8[tid >> 5] = s;
    __syncthreads();
    if (tid == 0) {
        float t = 0.f;
        #pragma unroll
        for (int i = 0; i < 8; i++) t += sm8[i];
        sstat = t * (1.0f / HID);
    }
    __syncthreads();
    const float mu = sstat;
    float d0 = v0 - mu, d1 = v1 - mu, d2 = v2 - mu;
    float qq = d0 * d0 + d1 * d1 + d2 * d2;
    #pragma unroll
    for (int off = 16; off; off >>= 1) qq += __shfl_xor_sync(0xffffffffu, qq, off);
    __syncthreads();
    if ((tid & 31) == 0) sm8[tid >> 5] = qq;
    __syncthreads();
    if (tid == 0) {
        float t = 0.f;
        #pragma unroll
        for (int i = 0; i < 8; i++) t += sm8[i];
        sstat = rsqrtf(t * (1.0f / HID) + 1e-5f);
    }
    __syncthreads();
    const float r = sstat;
    xs[tid]       = d0 * r * g[tid]       + b[tid];
    xs[tid + 256] = d1 * r * g[tid + 256] + b[tid + 256];
    xs[tid + 512] = d2 * r * g[tid + 512] + b[tid + 512];
    __syncthreads();

    for (int t = tid; t < 3 * HID; t += 256) {
        const int m = t / HID, rr = t % HID;
        const int hh = rr >> 5, e = rr & 31;
        const float* xp = xs + (hh << 5);
        const float* wp = &ws[m][e][0];
        float acc = 0.f;
        #pragma unroll
        for (int d = 0; d < 32; d++) acc = fmaf(xp[d], wp[d], acc);
        float* out = (m == 0) ? q : ((m == 1) ? k_ : v);
        out[(size_t)row * HID + rr] = tf32r(acc);
    }
}

// -------------------------------------------------- tensor-core attention
#define ATS 36    // qs/ks row stride (floats)
#define VTS 212   // vT row stride (floats)

__global__ __launch_bounds__(128, 2) void attn_tc_kernel(
    const float* __restrict__ q, const float* __restrict__ k,
    const float* __restrict__ v, const float* __restrict__ bias_mat,
    float* __restrict__ o)
{
    extern __shared__ float sm[];
    float* qs = sm;                       // LPAD*ATS = 7488
    float* ks = qs + LPAD * ATS;          // LPAD*ATS = 7488
    float* vT = ks + LPAD * ATS;          // 32*VTS   = 6784

    const int nb = blockIdx.x;
    const int n = nb / NH, h = nb % NH;
    const int tid = threadIdx.x, lane = tid & 31, warp = tid >> 5;
    const size_t base = (size_t)n * LL * HID + (size_t)h * HD;

    for (int t = tid; t < LL * HD; t += 128) {
        const int l = t >> 5, d = t & 31;
        const size_t g = base + (size_t)l * HID + d;
        qs[l * ATS + d] = q[g];
        ks[l * ATS + d] = k[g];
        vT[d * VTS + l] = v[g];
    }
    for (int t = tid; t < 12 * 32; t += 128)
        qs[(LL + (t >> 5)) * ATS + (t & 31)] = 0.f;
    for (int t = tid; t < 32 * 12; t += 128)
        vT[(t / 12) * VTS + LL + (t % 12)] = 0.f;
    __syncthreads();

    const float scale = 0.17677669529663687f;   // 1/sqrt(32)
    const int r = lane >> 2, jq = lane & 3;
    const int srcA = (lane & ~3) | (jq >> 1);
    const int srcB = srcA + 2;
    const bool odd = (jq & 1) != 0;

    for (int mt = warp; mt < 13; mt += 4) {
        const int row0 = mt * 16 + r;

        float sacc[26][4];
        #pragma unroll
        for (int nt = 0; nt < 26; nt++)
            #pragma unroll
            for (int e = 0; e < 4; e++) sacc[nt][e] = 0.f;

        #pragma unroll
        for (int kt = 0; kt < 4; kt++) {
            const int kb = kt * 8 + jq;
            const uint32_t a0 = __float_as_uint(qs[row0 * ATS + kb]);
            const uint32_t a1 = __float_as_uint(qs[(row0 + 8) * ATS + kb]);
            const uint32_t a2 = __float_as_uint(qs[row0 * ATS + kb + 4]);
            const uint32_t a3 = __float_as_uint(qs[(row0 + 8) * ATS + kb + 4]);
            #pragma unroll
            for (int nt = 0; nt < 26; nt++) {
                const int kr = (nt * 8 + r) * ATS + kb;
                const uint32_t b0 = __float_as_uint(ks[kr]);
                const uint32_t b1 = __float_as_uint(ks[kr + 4]);
                mma_tf32(sacc[nt], a0, a1, a2, a3, b0, b1);
            }
        }

        float mx0 = -1e30f, mx1 = -1e30f;
        #pragma unroll
        for (int nt = 0; nt < 26; nt++) {
            #pragma unroll
            for (int idx = 0; idx < 4; idx++) {
                const int e = idx & 1, half = idx >> 1;
                const int col = nt * 8 + 2 * jq + e;
                const int row = row0 + half * 8;
                float s;
                if (col < LL) {
                    s = (sacc[nt][idx] + bias_mat[row * LPAD + col]) * scale;
                } else {
                    s = -1e30f;
                }
                sacc[nt][idx] = s;
                if (half == 0) mx0 = fmaxf(mx0, s); else mx1 = fmaxf(mx1, s);
            }
        }
        mx0 = fmaxf(mx0, __shfl_xor_sync(0xffffffffu, mx0, 1));
        mx0 = fmaxf(mx0, __shfl_xor_sync(0xffffffffu, mx0, 2));
        mx1 = fmaxf(mx1, __shfl_xor_sync(0xffffffffu, mx1, 1));
        mx1 = fmaxf(mx1, __shfl_xor_sync(0xffffffffu, mx1, 2));

        float sum0 = 0.f, sum1 = 0.f;
        #pragma unroll
        for (int nt = 0; nt < 26; nt++) {
            #pragma unroll
            for (int idx = 0; idx < 4; idx++) {
                const int e = idx & 1, half = idx >> 1;
                const int col = nt * 8 + 2 * jq + e;
                float p = 0.f;
                if (col < LL) {
                    p = __expf(sacc[nt][idx] - (half ? mx1 : mx0));
                    if (half == 0) sum0 += p; else sum1 += p;
                }
                sacc[nt][idx] = p;
            }
        }
        sum0 += __shfl_xor_sync(0xffffffffu, sum0, 1);
        sum0 += __shfl_xor_sync(0xffffffffu, sum0, 2);
        sum1 += __shfl_xor_sync(0xffffffffu, sum1, 1);
        sum1 += __shfl_xor_sync(0xffffffffu, sum1, 2);
        const float inv0 = 1.0f / sum0, inv1 = 1.0f / sum1;

        float oacc[4][4];
        #pragma unroll
        for (int nt = 0; nt < 4; nt++)
            #pragma unroll
            for (int e = 0; e < 4; e++) oacc[nt][e] = 0.f;

        #pragma unroll
        for (int kt = 0; kt < 26; kt++) {
            const float x0 = __shfl_sync(0xffffffffu, sacc[kt][0], srcA);
            const float x1 = __shfl_sync(0xffffffffu, sacc[kt][1], srcA);
            const float x2 = __shfl_sync(0xffffffffu, sacc[kt][2], srcA);
            const float x3 = __shfl_sync(0xffffffffu, sacc[kt][3], srcA);
            const float y0 = __shfl_sync(0xffffffffu, sacc[kt][0], srcB);
            const float y1 = __shfl_sync(0xffffffffu, sacc[kt][1], srcB);
            const float y2 = __shfl_sync(0xffffffffu, sacc[kt][2], srcB);
            const float y3 = __shfl_sync(0xffffffffu, sacc[kt][3], srcB);
            const uint32_t a0 = __float_as_uint(odd ? x1 : x0);
            const uint32_t a1 = __float_as_uint(odd ? x3 : x2);
            const uint32_t a2 = __float_as_uint(odd ? y1 : y0);
            const uint32_t a3 = __float_as_uint(odd ? y3 : y2);
            const int kb = kt * 8 + jq;
            #pragma unroll
            for (int nt = 0; nt < 4; nt++) {
                const int vr = (nt * 8 + r) * VTS + kb;
                const uint32_t b0 = __float_as_uint(vT[vr]);
                const uint32_t b1 = __float_as_uint(vT[vr + 4]);
                mma_tf32(oacc[nt], a0, a1, a2, a3, b0, b1);
            }
        }

        #pragma unroll
        for (int nt = 0; nt < 4; nt++) {
            #pragma unroll
            for (int idx = 0; idx < 4; idx++) {
                const int e = idx & 1, half = idx >> 1;
                const int row = row0 + half * 8;
                const int col = nt * 8 + 2 * jq + e;
                if (row < LL) {
                    const float vv = oacc[nt][idx] * (half ? inv1 : inv0);
                    o[base + (size_t)row * HID + col] = tf32r(vv);
                }
            }
        }
    }
}

// ------------------------------------------------------------ tf32 TC GEMM
// 256 threads, 128x128x32 tile, 8 warps (4x2, warp tile 32x64), 2 blocks/SM.
// C[M,N] = A[M,K] @ B[N,K]^T (+bias); raw-bit tf32 operands (HW truncation on B).
//   mode 0: plain   1: exact gelu (out rounded)   2: (resid + val) * rate
#define TBM 128
#define TBN 128
#define TBK 32
#define TSTRIDE 36

#define CP_ASYNC16(dst, src) \
    asm volatile("cp.async.cg.shared.global [%0], [%1], 16;\n" :: "r"(dst), "l"(src))

__global__ __launch_bounds__(256, 2) void gemm_tc_kernel(
    const float* __restrict__ A, const float* __restrict__ B,
    const float* __restrict__ bias, const float* __restrict__ resid,
    float* __restrict__ C, int M, int N, int K, int mode, float rate)
{
    extern __shared__ float smg[];
    const int stageFloats = 2 * TBM * TSTRIDE;    // 9216 (A+B per stage)

    const int tid  = threadIdx.x;
    const int lane = tid & 31, warp = tid >> 5;
    const int wr = warp >> 1, wc = warp & 1;      // 4x2 warp grid
    const int bm = blockIdx.y * TBM, bn = blockIdx.x * TBN;

    const uint32_t smem_base = (uint32_t)__cvta_generic_to_shared(smg);
    const int nTiles = K / TBK;

    auto load_tile = [&](int kt, int s) {
        const float* Ag = A + (size_t)bm * K + (size_t)kt * TBK;
        const float* Bg = B + (size_t)bn * K + (size_t)kt * TBK;
        const uint32_t sA = smem_base + (uint32_t)(s * stageFloats) * 4u;
        const uint32_t sB = sA + (uint32_t)(TBM * TSTRIDE) * 4u;
        #pragma unroll
        for (int i = 0; i < 4; i++) {
            const int idx = i * 256 + tid;
            const int r = idx >> 3, c = idx & 7;
            CP_ASYNC16(sA + (uint32_t)(r * TSTRIDE * 4 + c * 16), Ag + (size_t)r * K + c * 4);
            CP_ASYNC16(sB + (uint32_t)(r * TSTRIDE * 4 + c * 16), Bg + (size_t)r * K + c * 4);
        }
    };

    float acc[2][8][4];
    #pragma unroll
    for (int i = 0; i < 2; i++)
        #pragma unroll
        for (int j = 0; j < 8; j++)
            #pragma unroll
            for (int r = 0; r < 4; r++) acc[i][j][r] = 0.f;

    const int aRow0 = wr * 32 + (lane >> 2);
    const int bRow0 = wc * 64 + (lane >> 2);
    const int kq = lane & 3;

    load_tile(0, 0);
    asm volatile("cp.async.commit_group;\n");

    for (int t = 0; t < nTiles; t++) {
        if (t + 1 < nTiles) {
            load_tile(t + 1, (t + 1) & 1);
            asm volatile("cp.async.commit_group;\n");
            asm volatile("cp.async.wait_group 1;\n");
        } else {
            asm volatile("cp.async.wait_group 0;\n");
        }
        __syncthreads();

        const uint32_t* As = (const uint32_t*)(smg + (t & 1) * stageFloats);
        const uint32_t* Bs = As + TBM * TSTRIDE;

        #pragma unroll
        for (int ks = 0; ks < 4; ks++) {
            const int kb = ks * 8 + kq;
            uint32_t bf[8][2];
            #pragma unroll
            for (int nt = 0; nt < 8; nt++) {
                const int rb = (bRow0 + nt * 8) * TSTRIDE + kb;
                bf[nt][0] = Bs[rb];
                bf[nt][1] = Bs[rb + 4];
            }
            #pragma unroll
            for (int mt = 0; mt < 2; mt++) {
                const int r0 = (aRow0 + mt * 16) * TSTRIDE + kb;
                const int r1 = r0 + 8 * TSTRIDE;
                const uint32_t a0 = As[r0];
                const uint32_t a1 = As[r1];
                const uint32_t a2 = As[r0 + 4];
                const uint32_t a3 = As[r1 + 4];
                #pragma unroll
                for (int nt = 0; nt < 8; nt++)
                    mma_tf32(acc[mt][nt], a0, a1, a2, a3, bf[nt][0], bf[nt][1]);
            }
        }
        __syncthreads();
    }

    // ------------------------------------------------------------- epilogue
    const int cRow0 = bm + wr * 32 + (lane >> 2);
    const int cCol0 = bn + wc * 64 + 2 * (lane & 3);
    #pragma unroll
    for (int mt = 0; mt < 2; mt++) {
        #pragma unroll
        for (int nt = 0; nt < 8; nt++) {
            #pragma unroll
            for (int half = 0; half < 2; half++) {
                const int row = cRow0 + mt * 16 + half * 8;
                #pragma unroll
                for (int e = 0; e < 2; e++) {
                    const int col = cCol0 + nt * 8 + e;
                    float vv = acc[mt][nt][half * 2 + e];
                    if (bias) vv += bias[col];
                    if (mode == 1) {
                        vv = 0.5f * vv * (1.0f + erff(vv * 0.70710678118654752f));
                        vv = tf32r(vv);      // feeds ffn2 A
                    } else if (mode == 2) {
                        vv = (resid[(size_t)row * N + col] + vv) * rate;
                    }
                    C[(size_t)row * N + col] = vv;
                }
            }
        }
    }
}

// --------------------------------------------------------------------- host
extern "C" void kernel_launch(void* const* d_in, const int* in_sizes, int n_in,
                              void* d_out, int out_size)
{
    const float* x        = (const float*)d_in[0];
    const float* rel_bias = (const float*)d_in[1];
    const float* wq       = (const float*)d_in[2];
    const float* wk       = (const float*)d_in[3];
    const float* wv       = (const float*)d_in[4];
    const float* w_out    = (const float*)d_in[5];
    const float* ln1_g    = (const float*)d_in[6];
    const float* ln1_b    = (const float*)d_in[7];
    const float* ln2_g    = (const float*)d_in[8];
    const float* ln2_b    = (const float*)d_in[9];
    const float* w1       = (const float*)d_in[10];
    const float* b1       = (const float*)d_in[11];
    const float* w2       = (const float*)d_in[12];
    const float* b2       = (const float*)d_in[13];
    float* out = (float*)d_out;

    float *p_ln, *p_q, *p_k, *p_v, *p_o, *p_h, *p_bias;
    cudaGetSymbolAddress((void**)&p_ln, g_ln);
    cudaGetSymbolAddress((void**)&p_q,  g_q);
    cudaGetSymbolAddress((void**)&p_k,  g_k);
    cudaGetSymbolAddress((void**)&p_v,  g_v);
    cudaGetSymbolAddress((void**)&p_o,  g_o);
    cudaGetSymbolAddress((void**)&p_h,  g_h);
    cudaGetSymbolAddress((void**)&p_bias, g_bias);

    const int attn_smem = (2 * LPAD * ATS + 32 * VTS) * (int)sizeof(float);  // 87040
    cudaFuncSetAttribute(attn_tc_kernel,
                         cudaFuncAttributeMaxDynamicSharedMemorySize, attn_smem);
    const int gemm_smem = 2 * 2 * TBM * TSTRIDE * (int)sizeof(float);  // 73728
    cudaFuncSetAttribute(gemm_tc_kernel,
                         cudaFuncAttributeMaxDynamicSharedMemorySize, gemm_smem);

    // 0) prep: build bias matrix
    bias_init_kernel<<<(LPAD * LPAD + 255) / 256, 256>>>(rel_bias, p_bias);

    // 1) fused ln1 + q/k/v projections
    ln_qkv_kernel<<<M_ROWS, 256>>>(x, ln1_g, ln1_b, wq, wk, wv, p_q, p_k, p_v);
    // 2) tensor-core attention
    attn_tc_kernel<<<NB * NH, 128, attn_smem>>>(p_q, p_k, p_v, p_bias, p_o);
    // 3) output projection + residual + rate -> d_out holds x1
    {
        dim3 grid(HID / TBN, M_ROWS / TBM);
        gemm_tc_kernel<<<grid, 256, gemm_smem>>>(p_o, w_out, nullptr, x, out,
                                                 M_ROWS, HID, HID, 2, RATE_F);
    }
    // 4) ln2
    ln_kernel<<<M_ROWS, 256>>>(out, ln2_g, ln2_b, p_ln);
    // 5) ffn1 + gelu (rounded output)
    {
        dim3 grid(FF / TBN, M_ROWS / TBM);
        gemm_tc_kernel<<<grid, 256, gemm_smem>>>(p_ln, w1, b1, nullptr, p_h,
                                                 M_ROWS, FF, HID, 1, 0.f);
    }
    // 6) ffn2 + residual + rate -> d_out final
    {
        dim3 grid(HID / TBN, M_ROWS / TBM);
        gemm_tc_kernel<<<grid, 256, gemm_smem>>>(p_h, w2, b2, out, out,
                                                 M_ROWS, HID, FF, 2, RATE_F);
    }
}

// round 9
// speedup vs baseline: 4.3275x; 1.2644x over previous
#include <cuda_runtime.h>
#include <cuda_bf16.h>
#include <cuda_fp16.h>
#include <math.h>
#include <stdint.h>

// Problem constants
#define NB     64
#define LL     196
#define HID    768
#define FF     3072
#define NH     24
#define HD     32
#define M_ROWS (NB * LL)          // 12544
#define RATE_F 0.2f
#define LPAD   208

// ---------------- scratch (static device globals; no runtime allocation) ----
__device__ float  g_ln[(size_t)M_ROWS * HID];     // ln2 fp32 (unused ffn path aux)
__device__ float  g_q [(size_t)M_ROWS * HID];
__device__ float  g_k [(size_t)M_ROWS * HID];
__device__ float  g_v [(size_t)M_ROWS * HID];
__device__ __half g_oh [(size_t)M_ROWS * HID];    // attention out (fp16)
__device__ __half g_lnh[(size_t)M_ROWS * HID];    // ln2 out (fp16)
__device__ __half g_hh [(size_t)M_ROWS * FF];     // gelu hidden (fp16)
__device__ __half g_wouth[HID * HID];
__device__ __half g_w1h[FF * HID];
__device__ __half g_w2h[HID * FF];
__device__ float  g_bias[LPAD * LPAD];

// ------------------------------------------------------------ helpers
__device__ __forceinline__ uint32_t f2tf(float f) {
    uint32_t r;
    asm("cvt.rna.tf32.f32 %0, %1;" : "=r"(r) : "f"(f));
    return r;
}
__device__ __forceinline__ float tf32r(float f) {
    return __uint_as_float(f2tf(f));
}
__device__ __forceinline__ void mma_tf32(
    float* c, uint32_t a0, uint32_t a1, uint32_t a2, uint32_t a3,
    uint32_t b0, uint32_t b1)
{
    asm volatile(
        "mma.sync.aligned.m16n8k8.row.col.f32.tf32.tf32.f32 "
        "{%0,%1,%2,%3}, {%4,%5,%6,%7}, {%8,%9}, {%0,%1,%2,%3};\n"
        : "+f"(c[0]), "+f"(c[1]), "+f"(c[2]), "+f"(c[3])
        : "r"(a0), "r"(a1), "r"(a2), "r"(a3), "r"(b0), "r"(b1));
}
__device__ __forceinline__ void mma_fp16(
    float* c, uint32_t a0, uint32_t a1, uint32_t a2, uint32_t a3,
    uint32_t b0, uint32_t b1)
{
    asm volatile(
        "mma.sync.aligned.m16n8k16.row.col.f32.f16.f16.f32 "
        "{%0,%1,%2,%3}, {%4,%5,%6,%7}, {%8,%9}, {%0,%1,%2,%3};\n"
        : "+f"(c[0]), "+f"(c[1]), "+f"(c[2]), "+f"(c[3])
        : "r"(a0), "r"(a1), "r"(a2), "r"(a3), "r"(b0), "r"(b1));
}

#define CP_ASYNC16(dst, src) \
    asm volatile("cp.async.cg.shared.global [%0], [%1], 16;\n" :: "r"(dst), "l"(src))

// ----------------------------------------------------- weight fp16 convert
__global__ __launch_bounds__(256) void conv_w_kernel(
    const float* __restrict__ w, __half* __restrict__ out, int n)
{
    int i = blockIdx.x * 256 + threadIdx.x;
    if (i < n) out[i] = __float2half_rn(w[i]);
}

// ----------------------------------------------------- bias matrix builder
__global__ __launch_bounds__(256) void bias_init_kernel(
    const float* __restrict__ rel_bias, float* __restrict__ bm)
{
    int idx = blockIdx.x * 256 + threadIdx.x;
    if (idx >= LPAD * LPAD) return;
    int row = idx / LPAD, col = idx % LPAD;
    float val = 0.f;
    if (row < LL && col < LL) {
        int qi = row / 14, qj = row % 14;
        int ki = col / 14, kj = col % 14;
        val = rel_bias[(qi - ki + 14) * 28 + (qj - kj + 14)];
    }
    bm[idx] = val;
}

// --------------------------------------------- LayerNorm (fp16 out for GEMM)
__global__ __launch_bounds__(256) void ln_kernel(
    const float* __restrict__ x, const float* __restrict__ g,
    const float* __restrict__ b, __half* __restrict__ y)
{
    __shared__ float sm8[8];
    __shared__ float sstat;
    const int row = blockIdx.x, tid = threadIdx.x;
    const float* xr = x + (size_t)row * HID;
    float v0 = xr[tid], v1 = xr[tid + 256], v2 = xr[tid + 512];
    float s = v0 + v1 + v2;
    #pragma unroll
    for (int off = 16; off; off >>= 1) s += __shfl_xor_sync(0xffffffffu, s, off);
    if ((tid & 31) == 0) sm8[tid >> 5] = s;
    __syncthreads();
    if (tid == 0) {
        float t = 0.f;
        #pragma unroll
        for (int i = 0; i < 8; i++) t += sm8[i];
        sstat = t * (1.0f / HID);
    }
    __syncthreads();
    const float mu = sstat;
    float d0 = v0 - mu, d1 = v1 - mu, d2 = v2 - mu;
    float q = d0 * d0 + d1 * d1 + d2 * d2;
    #pragma unroll
    for (int off = 16; off; off >>= 1) q += __shfl_xor_sync(0xffffffffu, q, off);
    __syncthreads();
    if ((tid & 31) == 0) sm8[tid >> 5] = q;
    __syncthreads();
    if (tid == 0) {
        float t = 0.f;
        #pragma unroll
        for (int i = 0; i < 8; i++) t += sm8[i];
        sstat = rsqrtf(t * (1.0f / HID) + 1e-5f);
    }
    __syncthreads();
    const float r = sstat;
    __half* yr = y + (size_t)row * HID;
    yr[tid]       = __float2half_rn(d0 * r * g[tid]       + b[tid]);
    yr[tid + 256] = __float2half_rn(d1 * r * g[tid + 256] + b[tid + 256]);
    yr[tid + 512] = __float2half_rn(d2 * r * g[tid + 512] + b[tid + 512]);
}

// ------------------------------------------ fused LayerNorm1 + QKV projection
__global__ __launch_bounds__(256) void ln_qkv_kernel(
    const float* __restrict__ x, const float* __restrict__ g,
    const float* __restrict__ b,
    const float* __restrict__ wq, const float* __restrict__ wk,
    const float* __restrict__ wv,
    float* __restrict__ q, float* __restrict__ k_, float* __restrict__ v)
{
    __shared__ float xs[HID];
    __shared__ float ws[3][32][33];
    __shared__ float sm8[8];
    __shared__ float sstat;
    const int row = blockIdx.x, tid = threadIdx.x;

    for (int t = tid; t < 1024; t += 256) {
        const int e = t >> 5, d = t & 31;
        ws[0][e][d] = wq[t];
        ws[1][e][d] = wk[t];
        ws[2][e][d] = wv[t];
    }

    const float* xr = x + (size_t)row * HID;
    float v0 = xr[tid], v1 = xr[tid + 256], v2 = xr[tid + 512];
    float s = v0 + v1 + v2;
    #pragma unroll
    for (int off = 16; off; off >>= 1) s += __shfl_xor_sync(0xffffffffu, s, off);
    if ((tid & 31) == 0) sm8[tid >> 5] = s;
    __syncthreads();
    if (tid == 0) {
        float t = 0.f;
        #pragma unroll
        for (int i = 0; i < 8; i++) t += sm8[i];
        sstat = t * (1.0f / HID);
    }
    __syncthreads();
    const float mu = sstat;
    float d0 = v0 - mu, d1 = v1 - mu, d2 = v2 - mu;
    float qq = d0 * d0 + d1 * d1 + d2 * d2;
    #pragma unroll
    for (int off = 16; off; off >>= 1) qq += __shfl_xor_sync(0xffffffffu, qq, off);
    __syncthreads();
    if ((tid & 31) == 0) sm8[tid >> 5] = qq;
    __syncthreads();
    if (tid == 0) {
        float t = 0.f;
        #pragma unroll
        for (int i = 0; i < 8; i++) t += sm8[i];
        sstat = rsqrtf(t * (1.0f / HID) + 1e-5f);
    }
    __syncthreads();
    const float r = sstat;
    xs[tid]       = d0 * r * g[tid]       + b[tid];
    xs[tid + 256] = d1 * r * g[tid + 256] + b[tid + 256];
    xs[tid + 512] = d2 * r * g[tid + 512] + b[tid + 512];
    __syncthreads();

    for (int t = tid; t < 3 * HID; t += 256) {
        const int m = t / HID, rr = t % HID;
        const int hh = rr >> 5, e = rr & 31;
        const float* xp = xs + (hh << 5);
        const float* wp = &ws[m][e][0];
        float acc = 0.f;
        #pragma unroll
        for (int d = 0; d < 32; d++) acc = fmaf(xp[d], wp[d], acc);
        float* out = (m == 0) ? q : ((m == 1) ? k_ : v);
        out[(size_t)row * HID + rr] = tf32r(acc);
    }
}

// -------------------------------------------------- tensor-core attention
#define ATS 36
#define VTS 212

__global__ __launch_bounds__(128, 2) void attn_tc_kernel(
    const float* __restrict__ q, const float* __restrict__ k,
    const float* __restrict__ v, const float* __restrict__ bias_mat,
    __half* __restrict__ o)
{
    extern __shared__ float sm[];
    float* qs = sm;
    float* ks = qs + LPAD * ATS;
    float* vT = ks + LPAD * ATS;

    const int nb = blockIdx.x;
    const int n = nb / NH, h = nb % NH;
    const int tid = threadIdx.x, lane = tid & 31, warp = tid >> 5;
    const size_t base = (size_t)n * LL * HID + (size_t)h * HD;

    for (int t = tid; t < LL * HD; t += 128) {
        const int l = t >> 5, d = t & 31;
        const size_t g = base + (size_t)l * HID + d;
        qs[l * ATS + d] = q[g];
        ks[l * ATS + d] = k[g];
        vT[d * VTS + l] = v[g];
    }
    for (int t = tid; t < 12 * 32; t += 128)
        qs[(LL + (t >> 5)) * ATS + (t & 31)] = 0.f;
    for (int t = tid; t < 32 * 12; t += 128)
        vT[(t / 12) * VTS + LL + (t % 12)] = 0.f;
    __syncthreads();

    const float scale = 0.17677669529663687f;
    const int r = lane >> 2, jq = lane & 3;
    const int srcA = (lane & ~3) | (jq >> 1);
    const int srcB = srcA + 2;
    const bool odd = (jq & 1) != 0;

    for (int mt = warp; mt < 13; mt += 4) {
        const int row0 = mt * 16 + r;

        float sacc[26][4];
        #pragma unroll
        for (int nt = 0; nt < 26; nt++)
            #pragma unroll
            for (int e = 0; e < 4; e++) sacc[nt][e] = 0.f;

        #pragma unroll
        for (int kt = 0; kt < 4; kt++) {
            const int kb = kt * 8 + jq;
            const uint32_t a0 = __float_as_uint(qs[row0 * ATS + kb]);
            const uint32_t a1 = __float_as_uint(qs[(row0 + 8) * ATS + kb]);
            const uint32_t a2 = __float_as_uint(qs[row0 * ATS + kb + 4]);
            const uint32_t a3 = __float_as_uint(qs[(row0 + 8) * ATS + kb + 4]);
            #pragma unroll
            for (int nt = 0; nt < 26; nt++) {
                const int kr = (nt * 8 + r) * ATS + kb;
                const uint32_t b0 = __float_as_uint(ks[kr]);
                const uint32_t b1 = __float_as_uint(ks[kr + 4]);
                mma_tf32(sacc[nt], a0, a1, a2, a3, b0, b1);
            }
        }

        float mx0 = -1e30f, mx1 = -1e30f;
        #pragma unroll
        for (int nt = 0; nt < 26; nt++) {
            #pragma unroll
            for (int idx = 0; idx < 4; idx++) {
                const int e = idx & 1, half = idx >> 1;
                const int col = nt * 8 + 2 * jq + e;
                const int row = row0 + half * 8;
                float s;
                if (col < LL) {
                    s = (sacc[nt][idx] + bias_mat[row * LPAD + col]) * scale;
                } else {
                    s = -1e30f;
                }
                sacc[nt][idx] = s;
                if (half == 0) mx0 = fmaxf(mx0, s); else mx1 = fmaxf(mx1, s);
            }
        }
        mx0 = fmaxf(mx0, __shfl_xor_sync(0xffffffffu, mx0, 1));
        mx0 = fmaxf(mx0, __shfl_xor_sync(0xffffffffu, mx0, 2));
        mx1 = fmaxf(mx1, __shfl_xor_sync(0xffffffffu, mx1, 1));
        mx1 = fmaxf(mx1, __shfl_xor_sync(0xffffffffu, mx1, 2));

        float sum0 = 0.f, sum1 = 0.f;
        #pragma unroll
        for (int nt = 0; nt < 26; nt++) {
            #pragma unroll
            for (int idx = 0; idx < 4; idx++) {
                const int e = idx & 1, half = idx >> 1;
                const int col = nt * 8 + 2 * jq + e;
                float p = 0.f;
                if (col < LL) {
                    p = __expf(sacc[nt][idx] - (half ? mx1 : mx0));
                    if (half == 0) sum0 += p; else sum1 += p;
                }
                sacc[nt][idx] = p;
            }
        }
        sum0 += __shfl_xor_sync(0xffffffffu, sum0, 1);
        sum0 += __shfl_xor_sync(0xffffffffu, sum0, 2);
        sum1 += __shfl_xor_sync(0xffffffffu, sum1, 1);
        sum1 += __shfl_xor_sync(0xffffffffu, sum1, 2);
        const float inv0 = 1.0f / sum0, inv1 = 1.0f / sum1;

        float oacc[4][4];
        #pragma unroll
        for (int nt = 0; nt < 4; nt++)
            #pragma unroll
            for (int e = 0; e < 4; e++) oacc[nt][e] = 0.f;

        #pragma unroll
        for (int kt = 0; kt < 26; kt++) {
            const float x0 = __shfl_sync(0xffffffffu, sacc[kt][0], srcA);
            const float x1 = __shfl_sync(0xffffffffu, sacc[kt][1], srcA);
            const float x2 = __shfl_sync(0xffffffffu, sacc[kt][2], srcA);
            const float x3 = __shfl_sync(0xffffffffu, sacc[kt][3], srcA);
            const float y0 = __shfl_sync(0xffffffffu, sacc[kt][0], srcB);
            const float y1 = __shfl_sync(0xffffffffu, sacc[kt][1], srcB);
            const float y2 = __shfl_sync(0xffffffffu, sacc[kt][2], srcB);
            const float y3 = __shfl_sync(0xffffffffu, sacc[kt][3], srcB);
            const uint32_t a0 = __float_as_uint(odd ? x1 : x0);
            const uint32_t a1 = __float_as_uint(odd ? x3 : x2);
            const uint32_t a2 = __float_as_uint(odd ? y1 : y0);
            const uint32_t a3 = __float_as_uint(odd ? y3 : y2);
            const int kb = kt * 8 + jq;
            #pragma unroll
            for (int nt = 0; nt < 4; nt++) {
                const int vr = (nt * 8 + r) * VTS + kb;
                const uint32_t b0 = __float_as_uint(vT[vr]);
                const uint32_t b1 = __float_as_uint(vT[vr + 4]);
                mma_tf32(oacc[nt], a0, a1, a2, a3, b0, b1);
            }
        }

        #pragma unroll
        for (int nt = 0; nt < 4; nt++) {
            #pragma unroll
            for (int idx = 0; idx < 4; idx++) {
                const int e = idx & 1, half = idx >> 1;
                const int row = row0 + half * 8;
                const int col = nt * 8 + 2 * jq + e;
                if (row < LL) {
                    const float vv = oacc[nt][idx] * (half ? inv1 : inv0);
                    o[base + (size_t)row * HID + col] = __float2half_rn(vv);
                }
            }
        }
    }
}

// ------------------------------------------------------------ fp16 TC GEMM
// C[M,N] = A[M,K] @ B[N,K]^T (+bias); fp16 operands, fp32 accumulate.
// 256 threads, 128x128x32 tile, 8 warps (4x2, warp tile 32x64).
//   mode 1: exact gelu -> Ch (half)    mode 2: (resid + val) * rate -> Cf
#define PSTR 20   // uint32 (half2-pair) stride per smem row: 16 data + 4 pad

__global__ __launch_bounds__(256, 2) void gemm_fp16_kernel(
    const __half* __restrict__ A, const __half* __restrict__ B,
    const float* __restrict__ bias, const float* __restrict__ resid,
    float* __restrict__ Cf, __half* __restrict__ Ch,
    int M, int N, int K, int mode, float rate)
{
    extern __shared__ uint32_t smh[];
    const int stageU32 = 2 * 128 * PSTR;      // A+B per stage = 5120 u32

    const int tid  = threadIdx.x;
    const int lane = tid & 31, warp = tid >> 5;
    const int wr = warp >> 1, wc = warp & 1;  // 4x2 warp grid
    const int bm = blockIdx.y * 128, bn = blockIdx.x * 128;

    const uint32_t smem_base = (uint32_t)__cvta_generic_to_shared(smh);
    const int nTiles = K / 32;

    auto load_tile = [&](int kt, int s) {
        const __half* Ag = A + (size_t)bm * K + (size_t)kt * 32;
        const __half* Bg = B + (size_t)bn * K + (size_t)kt * 32;
        const uint32_t sA = smem_base + (uint32_t)(s * stageU32) * 4u;
        const uint32_t sB = sA + (uint32_t)(128 * PSTR) * 4u;
        #pragma unroll
        for (int i = 0; i < 2; i++) {
            const int idx = i * 256 + tid;    // 512 16B chunks per operand
            const int r = idx >> 2, c = idx & 3;
            CP_ASYNC16(sA + (uint32_t)(r * PSTR * 4 + c * 16), Ag + (size_t)r * K + c * 8);
            CP_ASYNC16(sB + (uint32_t)(r * PSTR * 4 + c * 16), Bg + (size_t)r * K + c * 8);
        }
    };

    float acc[2][8][4];
    #pragma unroll
    for (int i = 0; i < 2; i++)
        #pragma unroll
        for (int j = 0; j < 8; j++)
            #pragma unroll
            for (int r = 0; r < 4; r++) acc[i][j][r] = 0.f;

    const int aRow0 = wr * 32 + (lane >> 2);
    const int bRow0 = wc * 64 + (lane >> 2);
    const int kq = lane & 3;

    load_tile(0, 0);
    asm volatile("cp.async.commit_group;\n");

    for (int t = 0; t < nTiles; t++) {
        if (t + 1 < nTiles) {
            load_tile(t + 1, (t + 1) & 1);
            asm volatile("cp.async.commit_group;\n");
            asm volatile("cp.async.wait_group 1;\n");
        } else {
            asm volatile("cp.async.wait_group 0;\n");
        }
        __syncthreads();

        const uint32_t* As = smh + (t & 1) * stageU32;
        const uint32_t* Bs = As + 128 * PSTR;

        #pragma unroll
        for (int ks = 0; ks < 2; ks++) {      // two k16 steps per 32-half tile
            const int kb = ks * 8 + kq;
            uint32_t bf[8][2];
            #pragma unroll
            for (int nt = 0; nt < 8; nt++) {
                const int rb = (bRow0 + nt * 8) * PSTR + kb;
                bf[nt][0] = Bs[rb];
                bf[nt][1] = Bs[rb + 4];
            }
            #pragma unroll
            for (int mt = 0; mt < 2; mt++) {
                const int r0 = (aRow0 + mt * 16) * PSTR + kb;
                const int r1 = r0 + 8 * PSTR;
                const uint32_t a0 = As[r0];
                const uint32_t a1 = As[r1];
                const uint32_t a2 = As[r0 + 4];
                const uint32_t a3 = As[r1 + 4];
                #pragma unroll
                for (int nt = 0; nt < 8; nt++)
                    mma_fp16(acc[mt][nt], a0, a1, a2, a3, bf[nt][0], bf[nt][1]);
            }
        }
        __syncthreads();
    }

    // ------------------------------------------------------------- epilogue
    const int cRow0 = bm + wr * 32 + (lane >> 2);
    const int cCol0 = bn + wc * 64 + 2 * (lane & 3);
    #pragma unroll
    for (int mt = 0; mt < 2; mt++) {
        #pragma unroll
        for (int nt = 0; nt < 8; nt++) {
            #pragma unroll
            for (int half = 0; half < 2; half++) {
                const int row = cRow0 + mt * 16 + half * 8;
                #pragma unroll
                for (int e = 0; e < 2; e++) {
                    const int col = cCol0 + nt * 8 + e;
                    float vv = acc[mt][nt][half * 2 + e];
                    if (bias) vv += bias[col];
                    if (mode == 1) {
                        vv = 0.5f * vv * (1.0f + erff(vv * 0.70710678118654752f));
                        Ch[(size_t)row * N + col] = __float2half_rn(vv);
                    } else {
                        vv = (resid[(size_t)row * N + col] + vv) * rate;
                        Cf[(size_t)row * N + col] = vv;
                    }
                }
            }
        }
    }
}

// --------------------------------------------------------------------- host
extern "C" void kernel_launch(void* const* d_in, const int* in_sizes, int n_in,
                              void* d_out, int out_size)
{
    const float* x        = (const float*)d_in[0];
    const float* rel_bias = (const float*)d_in[1];
    const float* wq       = (const float*)d_in[2];
    const float* wk       = (const float*)d_in[3];
    const float* wv       = (const float*)d_in[4];
    const float* w_out    = (const float*)d_in[5];
    const float* ln1_g    = (const float*)d_in[6];
    const float* ln1_b    = (const float*)d_in[7];
    const float* ln2_g    = (const float*)d_in[8];
    const float* ln2_b    = (const float*)d_in[9];
    const float* w1       = (const float*)d_in[10];
    const float* b1       = (const float*)d_in[11];
    const float* w2       = (const float*)d_in[12];
    const float* b2       = (const float*)d_in[13];
    float* out = (float*)d_out;

    float *p_q, *p_k, *p_v, *p_bias;
    __half *p_oh, *p_lnh, *p_hh, *p_wouth, *p_w1h, *p_w2h;
    cudaGetSymbolAddress((void**)&p_q,  g_q);
    cudaGetSymbolAddress((void**)&p_k,  g_k);
    cudaGetSymbolAddress((void**)&p_v,  g_v);
    cudaGetSymbolAddress((void**)&p_bias, g_bias);
    cudaGetSymbolAddress((void**)&p_oh,  g_oh);
    cudaGetSymbolAddress((void**)&p_lnh, g_lnh);
    cudaGetSymbolAddress((void**)&p_hh,  g_hh);
    cudaGetSymbolAddress((void**)&p_wouth, g_wouth);
    cudaGetSymbolAddress((void**)&p_w1h, g_w1h);
    cudaGetSymbolAddress((void**)&p_w2h, g_w2h);

    const int attn_smem = (2 * LPAD * ATS + 32 * VTS) * (int)sizeof(float);  // 87040
    cudaFuncSetAttribute(attn_tc_kernel,
                         cudaFuncAttributeMaxDynamicSharedMemorySize, attn_smem);
    const int gemm_smem = 2 * 2 * 128 * PSTR * 4;   // 40960
    cudaFuncSetAttribute(gemm_fp16_kernel,
                         cudaFuncAttributeMaxDynamicSharedMemorySize, gemm_smem);

    // 0) prep: fp16 weights, bias matrix
    conv_w_kernel<<<(HID * HID + 255) / 256, 256>>>(w_out, p_wouth, HID * HID);
    conv_w_kernel<<<(FF * HID + 255) / 256, 256>>>(w1, p_w1h, FF * HID);
    conv_w_kernel<<<(HID * FF + 255) / 256, 256>>>(w2, p_w2h, HID * FF);
    bias_init_kernel<<<(LPAD * LPAD + 255) / 256, 256>>>(rel_bias, p_bias);

    // 1) fused ln1 + q/k/v projections (fp32, tf32-rounded)
    ln_qkv_kernel<<<M_ROWS, 256>>>(x, ln1_g, ln1_b, wq, wk, wv, p_q, p_k, p_v);
    // 2) tensor-core attention -> fp16 o
    attn_tc_kernel<<<NB * NH, 128, attn_smem>>>(p_q, p_k, p_v, p_bias, p_oh);
    // 3) output projection + residual + rate -> d_out holds x1 (fp32)
    {
        dim3 grid(HID / 128, M_ROWS / 128);
        gemm_fp16_kernel<<<grid, 256, gemm_smem>>>(p_oh, p_wouth, nullptr, x,
                                                   out, nullptr,
                                                   M_ROWS, HID, HID, 2, RATE_F);
    }
    // 4) ln2 -> fp16
    ln_kernel<<<M_ROWS, 256>>>(out, ln2_g, ln2_b, p_lnh);
    // 5) ffn1 + gelu -> fp16 hidden
    {
        dim3 grid(FF / 128, M_ROWS / 128);
        gemm_fp16_kernel<<<grid, 256, gemm_smem>>>(p_lnh, p_w1h, b1, nullptr,
                                                   nullptr, p_hh,
                                                   M_ROWS, FF, HID, 1, 0.f);
    }
    // 6) ffn2 + residual + rate -> d_out final (fp32)
    {
        dim3 grid(HID / 128, M_ROWS / 128);
        gemm_fp16_kernel<<<grid, 256, gemm_smem>>>(p_hh, p_w2h, b2, out,
                                                   out, nullptr,
                                                   M_ROWS, HID, FF, 2, RATE_F);
    }
}

// round 10
// speedup vs baseline: 4.6681x; 1.0787x over previous
#include <cuda_runtime.h>
#include <cuda_bf16.h>
#include <cuda_fp16.h>
#include <math.h>
#include <stdint.h>

// Problem constants
#define NB     64
#define LL     196
#define HID    768
#define FF     3072
#define NH     24
#define HD     32
#define M_ROWS (NB * LL)          // 12544
#define RATE_F 0.2f
#define LPAD   208

// ---------------- scratch (static device globals; no runtime allocation) ----
__device__ __half g_qh[(size_t)M_ROWS * HID];
__device__ __half g_kh[(size_t)M_ROWS * HID];
__device__ __half g_vh[(size_t)M_ROWS * HID];
__device__ __half g_oh [(size_t)M_ROWS * HID];    // attention out (fp16)
__device__ __half g_lnh[(size_t)M_ROWS * HID];    // ln2 out (fp16)
__device__ __half g_hh [(size_t)M_ROWS * FF];     // gelu hidden (fp16)
__device__ __half g_wouth[HID * HID];
__device__ __half g_w1h[FF * HID];
__device__ __half g_w2h[HID * FF];
__device__ float  g_bias[LPAD * LPAD];

// ------------------------------------------------------------ helpers
__device__ __forceinline__ void mma_fp16(
    float* c, uint32_t a0, uint32_t a1, uint32_t a2, uint32_t a3,
    uint32_t b0, uint32_t b1)
{
    asm volatile(
        "mma.sync.aligned.m16n8k16.row.col.f32.f16.f16.f32 "
        "{%0,%1,%2,%3}, {%4,%5,%6,%7}, {%8,%9}, {%0,%1,%2,%3};\n"
        : "+f"(c[0]), "+f"(c[1]), "+f"(c[2]), "+f"(c[3])
        : "r"(a0), "r"(a1), "r"(a2), "r"(a3), "r"(b0), "r"(b1));
}
__device__ __forceinline__ uint32_t h2u(float lo, float hi) {
    __half2 h = __floats2half2_rn(lo, hi);
    return *reinterpret_cast<uint32_t*>(&h);
}

#define CP_ASYNC16(dst, src) \
    asm volatile("cp.async.cg.shared.global [%0], [%1], 16;\n" :: "r"(dst), "l"(src))

// ----------------------------------------------------- weight fp16 convert
__global__ __launch_bounds__(256) void conv_w_kernel(
    const float* __restrict__ w, __half* __restrict__ out, int n)
{
    int i = blockIdx.x * 256 + threadIdx.x;
    if (i < n) out[i] = __float2half_rn(w[i]);
}

// ----------------------------------------------------- bias matrix builder
__global__ __launch_bounds__(256) void bias_init_kernel(
    const float* __restrict__ rel_bias, float* __restrict__ bm)
{
    int idx = blockIdx.x * 256 + threadIdx.x;
    if (idx >= LPAD * LPAD) return;
    int row = idx / LPAD, col = idx % LPAD;
    float val = 0.f;
    if (row < LL && col < LL) {
        int qi = row / 14, qj = row % 14;
        int ki = col / 14, kj = col % 14;
        val = rel_bias[(qi - ki + 14) * 28 + (qj - kj + 14)];
    }
    bm[idx] = val;
}

// --------------------------------------------- LayerNorm (fp16 out for GEMM)
__global__ __launch_bounds__(256) void ln_kernel(
    const float* __restrict__ x, const float* __restrict__ g,
    const float* __restrict__ b, __half* __restrict__ y)
{
    __shared__ float sm8[8];
    __shared__ float sstat;
    const int row = blockIdx.x, tid = threadIdx.x;
    const float* xr = x + (size_t)row * HID;
    float v0 = xr[tid], v1 = xr[tid + 256], v2 = xr[tid + 512];
    float s = v0 + v1 + v2;
    #pragma unroll
    for (int off = 16; off; off >>= 1) s += __shfl_xor_sync(0xffffffffu, s, off);
    if ((tid & 31) == 0) sm8[tid >> 5] = s;
    __syncthreads();
    if (tid == 0) {
        float t = 0.f;
        #pragma unroll
        for (int i = 0; i < 8; i++) t += sm8[i];
        sstat = t * (1.0f / HID);
    }
    __syncthreads();
    const float mu = sstat;
    float d0 = v0 - mu, d1 = v1 - mu, d2 = v2 - mu;
    float q = d0 * d0 + d1 * d1 + d2 * d2;
    #pragma unroll
    for (int off = 16; off; off >>= 1) q += __shfl_xor_sync(0xffffffffu, q, off);
    __syncthreads();
    if ((tid & 31) == 0) sm8[tid >> 5] = q;
    __syncthreads();
    if (tid == 0) {
        float t = 0.f;
        #pragma unroll
        for (int i = 0; i < 8; i++) t += sm8[i];
        sstat = rsqrtf(t * (1.0f / HID) + 1e-5f);
    }
    __syncthreads();
    const float r = sstat;
    __half* yr = y + (size_t)row * HID;
    yr[tid]       = __float2half_rn(d0 * r * g[tid]       + b[tid]);
    yr[tid + 256] = __float2half_rn(d1 * r * g[tid + 256] + b[tid + 256]);
    yr[tid + 512] = __float2half_rn(d2 * r * g[tid + 512] + b[tid + 512]);
}

// ------------------------------------------ fused LayerNorm1 + QKV (fp16 out)
__global__ __launch_bounds__(256) void ln_qkv_kernel(
    const float* __restrict__ x, const float* __restrict__ g,
    const float* __restrict__ b,
    const float* __restrict__ wq, const float* __restrict__ wk,
    const float* __restrict__ wv,
    __half* __restrict__ q, __half* __restrict__ k_, __half* __restrict__ v)
{
    __shared__ float xs[HID];
    __shared__ float ws[3][32][33];
    __shared__ float sm8[8];
    __shared__ float sstat;
    const int row = blockIdx.x, tid = threadIdx.x;

    for (int t = tid; t < 1024; t += 256) {
        const int e = t >> 5, d = t & 31;
        ws[0][e][d] = wq[t];
        ws[1][e][d] = wk[t];
        ws[2][e][d] = wv[t];
    }

    const float* xr = x + (size_t)row * HID;
    float v0 = xr[tid], v1 = xr[tid + 256], v2 = xr[tid + 512];
    float s = v0 + v1 + v2;
    #pragma unroll
    for (int off = 16; off; off >>= 1) s += __shfl_xor_sync(0xffffffffu, s, off);
    if ((tid & 31) == 0) sm8[tid >> 5] = s;
    __syncthreads();
    if (tid == 0) {
        float t = 0.f;
        #pragma unroll
        for (int i = 0; i < 8; i++) t += sm8[i];
        sstat = t * (1.0f / HID);
    }
    __syncthreads();
    const float mu = sstat;
    float d0 = v0 - mu, d1 = v1 - mu, d2 = v2 - mu;
    float qq = d0 * d0 + d1 * d1 + d2 * d2;
    #pragma unroll
    for (int off = 16; off; off >>= 1) qq += __shfl_xor_sync(0xffffffffu, qq, off);
    __syncthreads();
    if ((tid & 31) == 0) sm8[tid >> 5] = qq;
    __syncthreads();
    if (tid == 0) {
        float t = 0.f;
        #pragma unroll
        for (int i = 0; i < 8; i++) t += sm8[i];
        sstat = rsqrtf(t * (1.0f / HID) + 1e-5f);
    }
    __syncthreads();
    const float r = sstat;
    xs[tid]       = d0 * r * g[tid]       + b[tid];
    xs[tid + 256] = d1 * r * g[tid + 256] + b[tid + 256];
    xs[tid + 512] = d2 * r * g[tid + 512] + b[tid + 512];
    __syncthreads();

    for (int t = tid; t < 3 * HID; t += 256) {
        const int m = t / HID, rr = t % HID;
        const int hh = rr >> 5, e = rr & 31;
        const float* xp = xs + (hh << 5);
        const float* wp = &ws[m][e][0];
        float acc = 0.f;
        #pragma unroll
        for (int d = 0; d < 32; d++) acc = fmaf(xp[d], wp[d], acc);
        __half* out = (m == 0) ? q : ((m == 1) ? k_ : v);
        out[(size_t)row * HID + rr] = __float2half_rn(acc);
    }
}

// ------------------------------------------------ fp16 tensor-core attention
// One block per (n, h), 4 warps, 3 blocks/SM (47 KB smem).
// S = Q K^T via m16n8k16 fp16 (2 k-steps), softmax fp32 in registers,
// P packed to A-fragments with plain half2 packs (no shuffles), O = P V.
#define QKS  20    // uint32 stride per qs/ks row (40 halves: 32 data + 8 pad)
#define VTS5 108   // uint32 stride per vT row (216 halves: 208 data + 8 pad)

__global__ __launch_bounds__(128, 3) void attn_fp16_kernel(
    const __half* __restrict__ q, const __half* __restrict__ k,
    const __half* __restrict__ v, const float* __restrict__ bias_mat,
    __half* __restrict__ o)
{
    extern __shared__ uint32_t smA[];
    uint32_t* qs = smA;                  // LPAD*QKS = 4160 u32
    uint32_t* ks = qs + LPAD * QKS;      // 4160
    uint32_t* vT = ks + LPAD * QKS;      // 32*108 = 3456  (total 47104 B)

    const int nb = blockIdx.x;
    const int n = nb / NH, h = nb % NH;
    const int tid = threadIdx.x, lane = tid & 31, warp = tid >> 5;
    const size_t base = (size_t)n * LL * HID + (size_t)h * HD;

    // stage Q,K rows ([token][dim], half2-packed) and V^T ([dim][token])
    {
        const uint32_t* qg = (const uint32_t*)(q + base);
        const uint32_t* kg = (const uint32_t*)(k + base);
        for (int t = tid; t < LL * 16; t += 128) {
            const int l = t >> 4, dp = t & 15;
            qs[l * QKS + dp] = qg[l * (HID / 2) + dp];
            ks[l * QKS + dp] = kg[l * (HID / 2) + dp];
        }
        __half* vh = (__half*)vT;
        for (int t = tid; t < LL * HD; t += 128) {
            const int l = t >> 5, d = t & 31;
            vh[d * 216 + l] = v[base + (size_t)l * HID + d];
        }
        for (int t = tid; t < 12 * 16; t += 128)
            qs[(LL + (t >> 4)) * QKS + (t & 15)] = 0;
        for (int t = tid; t < 32 * 12; t += 128)
            vh[(t / 12) * 216 + LL + (t % 12)] = __float2half_rn(0.f);
    }
    __syncthreads();

    const float scale = 0.17677669529663687f;   // 1/sqrt(32)
    const int r = lane >> 2, jq = lane & 3;

    for (int mt = warp; mt < 13; mt += 4) {
        const int row0 = mt * 16 + r;

        // ---- S = Q K^T  (26 n-tiles over keys, 2 fp16 k16-steps)
        float sacc[26][4];
        #pragma unroll
        for (int nt = 0; nt < 26; nt++)
            #pragma unroll
            for (int e = 0; e < 4; e++) sacc[nt][e] = 0.f;

        #pragma unroll
        for (int kt = 0; kt < 2; kt++) {
            const int kb = kt * 8 + jq;
            const uint32_t a0 = qs[row0 * QKS + kb];
            const uint32_t a1 = qs[(row0 + 8) * QKS + kb];
            const uint32_t a2 = qs[row0 * QKS + kb + 4];
            const uint32_t a3 = qs[(row0 + 8) * QKS + kb + 4];
            #pragma unroll
            for (int nt = 0; nt < 26; nt++) {
                const int kr = (nt * 8 + r) * QKS + kb;
                const uint32_t b0 = ks[kr];
                const uint32_t b1 = ks[kr + 4];
                mma_fp16(sacc[nt], a0, a1, a2, a3, b0, b1);
            }
        }

        // ---- bias + scale + masked row-max
        float mx0 = -1e30f, mx1 = -1e30f;
        #pragma unroll
        for (int nt = 0; nt < 26; nt++) {
            #pragma unroll
            for (int idx = 0; idx < 4; idx++) {
                const int e = idx & 1, half = idx >> 1;
                const int col = nt * 8 + 2 * jq + e;
                const int row = row0 + half * 8;
                float s;
                if (col < LL) {
                    s = (sacc[nt][idx] + bias_mat[row * LPAD + col]) * scale;
                } else {
                    s = -1e30f;
                }
                sacc[nt][idx] = s;
                if (half == 0) mx0 = fmaxf(mx0, s); else mx1 = fmaxf(mx1, s);
            }
        }
        mx0 = fmaxf(mx0, __shfl_xor_sync(0xffffffffu, mx0, 1));
        mx0 = fmaxf(mx0, __shfl_xor_sync(0xffffffffu, mx0, 2));
        mx1 = fmaxf(mx1, __shfl_xor_sync(0xffffffffu, mx1, 1));
        mx1 = fmaxf(mx1, __shfl_xor_sync(0xffffffffu, mx1, 2));

        // ---- exp in registers (unnormalized P; zero at pad cols)
        float sum0 = 0.f, sum1 = 0.f;
        #pragma unroll
        for (int nt = 0; nt < 26; nt++) {
            #pragma unroll
            for (int idx = 0; idx < 4; idx++) {
                const int e = idx & 1, half = idx >> 1;
                const int col = nt * 8 + 2 * jq + e;
                float p = 0.f;
                if (col < LL) {
                    p = __expf(sacc[nt][idx] - (half ? mx1 : mx0));
                    if (half == 0) sum0 += p; else sum1 += p;
                }
                sacc[nt][idx] = p;
            }
        }
        sum0 += __shfl_xor_sync(0xffffffffu, sum0, 1);
        sum0 += __shfl_xor_sync(0xffffffffu, sum0, 2);
        sum1 += __shfl_xor_sync(0xffffffffu, sum1, 1);
        sum1 += __shfl_xor_sync(0xffffffffu, sum1, 2);
        const float inv0 = 1.0f / sum0, inv1 = 1.0f / sum1;

        // ---- O = P V (13 fp16 k16-steps); A-frags are direct half2 packs
        float oacc[4][4];
        #pragma unroll
        for (int nt = 0; nt < 4; nt++)
            #pragma unroll
            for (int e = 0; e < 4; e++) oacc[nt][e] = 0.f;

        #pragma unroll
        for (int kt = 0; kt < 13; kt++) {
            const uint32_t a0 = h2u(sacc[2 * kt][0],     sacc[2 * kt][1]);
            const uint32_t a1 = h2u(sacc[2 * kt][2],     sacc[2 * kt][3]);
            const uint32_t a2 = h2u(sacc[2 * kt + 1][0], sacc[2 * kt + 1][1]);
            const uint32_t a3 = h2u(sacc[2 * kt + 1][2], sacc[2 * kt + 1][3]);
            const int kb = kt * 8 + jq;
            #pragma unroll
            for (int nt = 0; nt < 4; nt++) {
                const int vr = (nt * 8 + r) * VTS5 + kb;
                const uint32_t b0 = vT[vr];
                const uint32_t b1 = vT[vr + 4];
                mma_fp16(oacc[nt], a0, a1, a2, a3, b0, b1);
            }
        }

        // ---- store O (fp16, feeds w_out GEMM)
        #pragma unroll
        for (int nt = 0; nt < 4; nt++) {
            #pragma unroll
            for (int idx = 0; idx < 4; idx++) {
                const int e = idx & 1, half = idx >> 1;
                const int row = row0 + half * 8;
                const int col = nt * 8 + 2 * jq + e;
                if (row < LL) {
                    const float vv = oacc[nt][idx] * (half ? inv1 : inv0);
                    o[base + (size_t)row * HID + col] = __float2half_rn(vv);
                }
            }
        }
    }
}

// ------------------------------------------------------------ fp16 TC GEMM
// C[M,N] = A[M,K] @ B[N,K]^T (+bias); fp16 operands, fp32 accumulate.
//   mode 1: exact gelu -> Ch (half)    mode 2: (resid + val) * rate -> Cf
#define PSTR 20   // uint32 stride per smem row: 16 data + 4 pad

__global__ __launch_bounds__(256, 2) void gemm_fp16_kernel(
    const __half* __restrict__ A, const __half* __restrict__ B,
    const float* __restrict__ bias, const float* __restrict__ resid,
    float* __restrict__ Cf, __half* __restrict__ Ch,
    int M, int N, int K, int mode, float rate)
{
    extern __shared__ uint32_t smh[];
    const int stageU32 = 2 * 128 * PSTR;

    const int tid  = threadIdx.x;
    const int lane = tid & 31, warp = tid >> 5;
    const int wr = warp >> 1, wc = warp & 1;
    const int bm = blockIdx.y * 128, bn = blockIdx.x * 128;

    const uint32_t smem_base = (uint32_t)__cvta_generic_to_shared(smh);
    const int nTiles = K / 32;

    auto load_tile = [&](int kt, int s) {
        const __half* Ag = A + (size_t)bm * K + (size_t)kt * 32;
        const __half* Bg = B + (size_t)bn * K + (size_t)kt * 32;
        const uint32_t sA = smem_base + (uint32_t)(s * stageU32) * 4u;
        const uint32_t sB = sA + (uint32_t)(128 * PSTR) * 4u;
        #pragma unroll
        for (int i = 0; i < 2; i++) {
            const int idx = i * 256 + tid;
            const int r = idx >> 2, c = idx & 3;
            CP_ASYNC16(sA + (uint32_t)(r * PSTR * 4 + c * 16), Ag + (size_t)r * K + c * 8);
            CP_ASYNC16(sB + (uint32_t)(r * PSTR * 4 + c * 16), Bg + (size_t)r * K + c * 8);
        }
    };

    float acc[2][8][4];
    #pragma unroll
    for (int i = 0; i < 2; i++)
        #pragma unroll
        for (int j = 0; j < 8; j++)
            #pragma unroll
            for (int r = 0; r < 4; r++) acc[i][j][r] = 0.f;

    const int aRow0 = wr * 32 + (lane >> 2);
    const int bRow0 = wc * 64 + (lane >> 2);
    const int kq = lane & 3;

    load_tile(0, 0);
    asm volatile("cp.async.commit_group;\n");

    for (int t = 0; t < nTiles; t++) {
        if (t + 1 < nTiles) {
            load_tile(t + 1, (t + 1) & 1);
            asm volatile("cp.async.commit_group;\n");
            asm volatile("cp.async.wait_group 1;\n");
        } else {
            asm volatile("cp.async.wait_group 0;\n");
        }
        __syncthreads();

        const uint32_t* As = smh + (t & 1) * stageU32;
        const uint32_t* Bs = As + 128 * PSTR;

        #pragma unroll
        for (int ks = 0; ks < 2; ks++) {
            const int kb = ks * 8 + kq;
            uint32_t bf[8][2];
            #pragma unroll
            for (int nt = 0; nt < 8; nt++) {
                const int rb = (bRow0 + nt * 8) * PSTR + kb;
                bf[nt][0] = Bs[rb];
                bf[nt][1] = Bs[rb + 4];
            }
            #pragma unroll
            for (int mt = 0; mt < 2; mt++) {
                const int r0 = (aRow0 + mt * 16) * PSTR + kb;
                const int r1 = r0 + 8 * PSTR;
                const uint32_t a0 = As[r0];
                const uint32_t a1 = As[r1];
                const uint32_t a2 = As[r0 + 4];
                const uint32_t a3 = As[r1 + 4];
                #pragma unroll
                for (int nt = 0; nt < 8; nt++)
                    mma_fp16(acc[mt][nt], a0, a1, a2, a3, bf[nt][0], bf[nt][1]);
            }
        }
        __syncthreads();
    }

    const int cRow0 = bm + wr * 32 + (lane >> 2);
    const int cCol0 = bn + wc * 64 + 2 * (lane & 3);
    #pragma unroll
    for (int mt = 0; mt < 2; mt++) {
        #pragma unroll
        for (int nt = 0; nt < 8; nt++) {
            #pragma unroll
            for (int half = 0; half < 2; half++) {
                const int row = cRow0 + mt * 16 + half * 8;
                #pragma unroll
                for (int e = 0; e < 2; e++) {
                    const int col = cCol0 + nt * 8 + e;
                    float vv = acc[mt][nt][half * 2 + e];
                    if (bias) vv += bias[col];
                    if (mode == 1) {
                        vv = 0.5f * vv * (1.0f + erff(vv * 0.70710678118654752f));
                        Ch[(size_t)row * N + col] = __float2half_rn(vv);
                    } else {
                        vv = (resid[(size_t)row * N + col] + vv) * rate;
                        Cf[(size_t)row * N + col] = vv;
                    }
                }
            }
        }
    }
}

// --------------------------------------------------------------------- host
extern "C" void kernel_launch(void* const* d_in, const int* in_sizes, int n_in,
                              void* d_out, int out_size)
{
    const float* x        = (const float*)d_in[0];
    const float* rel_bias = (const float*)d_in[1];
    const float* wq       = (const float*)d_in[2];
    const float* wk       = (const float*)d_in[3];
    const float* wv       = (const float*)d_in[4];
    const float* w_out    = (const float*)d_in[5];
    const float* ln1_g    = (const float*)d_in[6];
    const float* ln1_b    = (const float*)d_in[7];
    const float* ln2_g    = (const float*)d_in[8];
    const float* ln2_b    = (const float*)d_in[9];
    const float* w1       = (const float*)d_in[10];
    const float* b1       = (const float*)d_in[11];
    const float* w2       = (const float*)d_in[12];
    const float* b2       = (const float*)d_in[13];
    float* out = (float*)d_out;

    float *p_bias;
    __half *p_qh, *p_kh, *p_vh, *p_oh, *p_lnh, *p_hh, *p_wouth, *p_w1h, *p_w2h;
    cudaGetSymbolAddress((void**)&p_bias, g_bias);
    cudaGetSymbolAddress((void**)&p_qh, g_qh);
    cudaGetSymbolAddress((void**)&p_kh, g_kh);
    cudaGetSymbolAddress((void**)&p_vh, g_vh);
    cudaGetSymbolAddress((void**)&p_oh,  g_oh);
    cudaGetSymbolAddress((void**)&p_lnh, g_lnh);
    cudaGetSymbolAddress((void**)&p_hh,  g_hh);
    cudaGetSymbolAddress((void**)&p_wouth, g_wouth);
    cudaGetSymbolAddress((void**)&p_w1h, g_w1h);
    cudaGetSymbolAddress((void**)&p_w2h, g_w2h);

    const int attn_smem = (2 * LPAD * QKS + 32 * VTS5) * 4;   // 47104
    cudaFuncSetAttribute(attn_fp16_kernel,
                         cudaFuncAttributeMaxDynamicSharedMemorySize, attn_smem);
    const int gemm_smem = 2 * 2 * 128 * PSTR * 4;             // 40960
    cudaFuncSetAttribute(gemm_fp16_kernel,
                         cudaFuncAttributeMaxDynamicSharedMemorySize, gemm_smem);

    // 0) prep: fp16 weights, bias matrix
    conv_w_kernel<<<(HID * HID + 255) / 256, 256>>>(w_out, p_wouth, HID * HID);
    conv_w_kernel<<<(FF * HID + 255) / 256, 256>>>(w1, p_w1h, FF * HID);
    conv_w_kernel<<<(HID * FF + 255) / 256, 256>>>(w2, p_w2h, HID * FF);
    bias_init_kernel<<<(LPAD * LPAD + 255) / 256, 256>>>(rel_bias, p_bias);

    // 1) fused ln1 + q/k/v projections (fp16 out)
    ln_qkv_kernel<<<M_ROWS, 256>>>(x, ln1_g, ln1_b, wq, wk, wv, p_qh, p_kh, p_vh);
    // 2) fp16 tensor-core attention -> fp16 o
    attn_fp16_kernel<<<NB * NH, 128, attn_smem>>>(p_qh, p_kh, p_vh, p_bias, p_oh);
    // 3) output projection + residual + rate -> d_out holds x1 (fp32)
    {
        dim3 grid(HID / 128, M_ROWS / 128);
        gemm_fp16_kernel<<<grid, 256, gemm_smem>>>(p_oh, p_wouth, nullptr, x,
                                                   out, nullptr,
                                                   M_ROWS, HID, HID, 2, RATE_F);
    }
    // 4) ln2 -> fp16
    ln_kernel<<<M_ROWS, 256>>>(out, ln2_g, ln2_b, p_lnh);
    // 5) ffn1 + gelu -> fp16 hidden
    {
        dim3 grid(FF / 128, M_ROWS / 128);
        gemm_fp16_kernel<<<grid, 256, gemm_smem>>>(p_lnh, p_w1h, b1, nullptr,
                                                   nullptr, p_hh,
                                                   M_ROWS, FF, HID, 1, 0.f);
    }
    // 6) ffn2 + residual + rate -> d_out final (fp32)
    {
        dim3 grid(HID / 128, M_ROWS / 128);
        gemm_fp16_kernel<<<grid, 256, gemm_smem>>>(p_hh, p_w2h, b2, out,
                                                   out, nullptr,
                                                   M_ROWS, HID, FF, 2, RATE_F);
    }
}

// round 14
// speedup vs baseline: 4.8225x; 1.0331x over previous
#include <cuda_runtime.h>
#include <cuda_bf16.h>
#include <cuda_fp16.h>
#include <math.h>
#include <stdint.h>

// Problem constants
#define NB     64
#define LL     196
#define HID    768
#define FF     3072
#define NH     24
#define HD     32
#define M_ROWS (NB * LL)          // 12544
#define RATE_F 0.2f
#define LPAD   208

// ---------------- scratch (static device globals; no runtime allocation) ----
__device__ __half g_qh[(size_t)M_ROWS * HID];
__device__ __half g_kh[(size_t)M_ROWS * HID];
__device__ __half g_vh[(size_t)M_ROWS * HID];
__device__ __half g_oh [(size_t)M_ROWS * HID];
__device__ __half g_lnh[(size_t)M_ROWS * HID];
__device__ __half g_hh [(size_t)M_ROWS * FF];
__device__ __half g_wouth[HID * HID];
__device__ __half g_w1h[FF * HID];
__device__ __half g_w2h[HID * FF];
__device__ float  g_bias[LPAD * LPAD];

// ------------------------------------------------------------ helpers
__device__ __forceinline__ void mma_fp16(
    float* c, uint32_t a0, uint32_t a1, uint32_t a2, uint32_t a3,
    uint32_t b0, uint32_t b1)
{
    asm volatile(
        "mma.sync.aligned.m16n8k16.row.col.f32.f16.f16.f32 "
        "{%0,%1,%2,%3}, {%4,%5,%6,%7}, {%8,%9}, {%0,%1,%2,%3};\n"
        : "+f"(c[0]), "+f"(c[1]), "+f"(c[2]), "+f"(c[3])
        : "r"(a0), "r"(a1), "r"(a2), "r"(a3), "r"(b0), "r"(b1));
}
__device__ __forceinline__ uint32_t h2u(float lo, float hi) {
    __half2 h = __floats2half2_rn(lo, hi);
    return *reinterpret_cast<uint32_t*>(&h);
}

#define CP_ASYNC16(dst, src) \
    asm volatile("cp.async.cg.shared.global [%0], [%1], 16;\n" :: "r"(dst), "l"(src))

#define LDSM_X4(r, addr) \
    asm volatile("ldmatrix.sync.aligned.m8n8.x4.shared.b16 {%0,%1,%2,%3}, [%4];" \
        : "=r"((r)[0]), "=r"((r)[1]), "=r"((r)[2]), "=r"((r)[3]) : "r"(addr))

// ----------------------------------------------------- weight fp16 convert
__global__ __launch_bounds__(256) void conv_w_kernel(
    const float* __restrict__ w, __half* __restrict__ out, int n)
{
    int i = blockIdx.x * 256 + threadIdx.x;
    if (i < n) out[i] = __float2half_rn(w[i]);
}

// ----------------------------------------------------- bias matrix builder
__global__ __launch_bounds__(256) void bias_init_kernel(
    const float* __restrict__ rel_bias, float* __restrict__ bm)
{
    int idx = blockIdx.x * 256 + threadIdx.x;
    if (idx >= LPAD * LPAD) return;
    int row = idx / LPAD, col = idx % LPAD;
    float val = 0.f;
    if (row < LL && col < LL) {
        int qi = row / 14, qj = row % 14;
        int ki = col / 14, kj = col % 14;
        val = rel_bias[(qi - ki + 14) * 28 + (qj - kj + 14)];
    }
    bm[idx] = val;
}

// --------------------------------------------- LayerNorm (fp16 out for GEMM)
__global__ __launch_bounds__(256) void ln_kernel(
    const float* __restrict__ x, const float* __restrict__ g,
    const float* __restrict__ b, __half* __restrict__ y)
{
    __shared__ float sm8[8];
    __shared__ float sstat;
    const int row = blockIdx.x, tid = threadIdx.x;
    const float* xr = x + (size_t)row * HID;
    float v0 = xr[tid], v1 = xr[tid + 256], v2 = xr[tid + 512];
    float s = v0 + v1 + v2;
    #pragma unroll
    for (int off = 16; off; off >>= 1) s += __shfl_xor_sync(0xffffffffu, s, off);
    if ((tid & 31) == 0) sm8[tid >> 5] = s;
    __syncthreads();
    if (tid == 0) {
        float t = 0.f;
        #pragma unroll
        for (int i = 0; i < 8; i++) t += sm8[i];
        sstat = t * (1.0f / HID);
    }
    __syncthreads();
    const float mu = sstat;
    float d0 = v0 - mu, d1 = v1 - mu, d2 = v2 - mu;
    float q = d0 * d0 + d1 * d1 + d2 * d2;
    #pragma unroll
    for (int off = 16; off; off >>= 1) q += __shfl_xor_sync(0xffffffffu, q, off);
    __syncthreads();
    if ((tid & 31) == 0) sm8[tid >> 5] = q;
    __syncthreads();
    if (tid == 0) {
        float t = 0.f;
        #pragma unroll
        for (int i = 0; i < 8; i++) t += sm8[i];
        sstat = rsqrtf(t * (1.0f / HID) + 1e-5f);
    }
    __syncthreads();
    const float r = sstat;
    __half* yr = y + (size_t)row * HID;
    yr[tid]       = __float2half_rn(d0 * r * g[tid]       + b[tid]);
    yr[tid + 256] = __float2half_rn(d1 * r * g[tid + 256] + b[tid + 256]);
    yr[tid + 512] = __float2half_rn(d2 * r * g[tid + 512] + b[tid + 512]);
}

// ------------------------------------------ fused LayerNorm1 + QKV (fp16 out)
__global__ __launch_bounds__(256) void ln_qkv_kernel(
    const float* __restrict__ x, const float* __restrict__ g,
    const float* __restrict__ b,
    const float* __restrict__ wq, const float* __restrict__ wk,
    const float* __restrict__ wv,
    __half* __restrict__ q, __half* __restrict__ k_, __half* __restrict__ v)
{
    __shared__ float xs[HID];
    __shared__ float ws[3][32][33];
    __shared__ float sm8[8];
    __shared__ float sstat;
    const int row = blockIdx.x, tid = threadIdx.x;

    for (int t = tid; t < 1024; t += 256) {
        const int e = t >> 5, d = t & 31;
        ws[0][e][d] = wq[t];
        ws[1][e][d] = wk[t];
        ws[2][e][d] = wv[t];
    }

    const float* xr = x + (size_t)row * HID;
    float v0 = xr[tid], v1 = xr[tid + 256], v2 = xr[tid + 512];
    float s = v0 + v1 + v2;
    #pragma unroll
    for (int off = 16; off; off >>= 1) s += __shfl_xor_sync(0xffffffffu, s, off);
    if ((tid & 31) == 0) sm8[tid >> 5] = s;
    __syncthreads();
    if (tid == 0) {
        float t = 0.f;
        #pragma unroll
        for (int i = 0; i < 8; i++) t += sm8[i];
        sstat = t * (1.0f / HID);
    }
    __syncthreads();
    const float mu = sstat;
    float d0 = v0 - mu, d1 = v1 - mu, d2 = v2 - mu;
    float qq = d0 * d0 + d1 * d1 + d2 * d2;
    #pragma unroll
    for (int off = 16; off; off >>= 1) qq += __shfl_xor_sync(0xffffffffu, qq, off);
    __syncthreads();
    if ((tid & 31) == 0) sm8[tid >> 5] = qq;
    __syncthreads();
    if (tid == 0) {
        float t = 0.f;
        #pragma unroll
        for (int i = 0; i < 8; i++) t += sm8[i];
        sstat = rsqrtf(t * (1.0f / HID) + 1e-5f);
    }
    __syncthreads();
    const float r = sstat;
    xs[tid]       = d0 * r * g[tid]       + b[tid];
    xs[tid + 256] = d1 * r * g[tid + 256] + b[tid + 256];
    xs[tid + 512] = d2 * r * g[tid + 512] + b[tid + 512];
    __syncthreads();

    for (int t = tid; t < 3 * HID; t += 256) {
        const int m = t / HID, rr = t % HID;
        const int hh = rr >> 5, e = rr & 31;
        const float* xp = xs + (hh << 5);
        const float* wp = &ws[m][e][0];
        float acc = 0.f;
        #pragma unroll
        for (int d = 0; d < 32; d++) acc = fmaf(xp[d], wp[d], acc);
        __half* out = (m == 0) ? q : ((m == 1) ? k_ : v);
        out[(size_t)row * HID + rr] = __float2half_rn(acc);
    }
}

// ------------------------------------------------ fp16 tensor-core attention
#define QKS  20    // uint32 stride per qs/ks row (40 halves)
#define VTS5 108   // uint32 stride per vT row (216 halves)

__global__ __launch_bounds__(128, 3) void attn_fp16_kernel(
    const __half* __restrict__ q, const __half* __restrict__ k,
    const __half* __restrict__ v, const float* __restrict__ bias_mat,
    __half* __restrict__ o)
{
    extern __shared__ uint32_t smA[];
    uint32_t* qs = smA;
    uint32_t* ks = qs + LPAD * QKS;
    uint32_t* vT = ks + LPAD * QKS;

    const int nb = blockIdx.x;
    const int n = nb / NH, h = nb % NH;
    const int tid = threadIdx.x, lane = tid & 31, warp = tid >> 5;
    const size_t base = (size_t)n * LL * HID + (size_t)h * HD;

    {
        const uint32_t* qg = (const uint32_t*)(q + base);
        const uint32_t* kg = (const uint32_t*)(k + base);
        for (int t = tid; t < LL * 16; t += 128) {
            const int l = t >> 4, dp = t & 15;
            qs[l * QKS + dp] = qg[l * (HID / 2) + dp];
            ks[l * QKS + dp] = kg[l * (HID / 2) + dp];
        }
        __half* vh = (__half*)vT;
        for (int t = tid; t < LL * HD; t += 128) {
            const int l = t >> 5, d = t & 31;
            vh[d * 216 + l] = v[base + (size_t)l * HID + d];
        }
        for (int t = tid; t < 12 * 16; t += 128)
            qs[(LL + (t >> 4)) * QKS + (t & 15)] = 0;
        for (int t = tid; t < 32 * 12; t += 128)
            vh[(t / 12) * 216 + LL + (t % 12)] = __float2half_rn(0.f);
    }
    __syncthreads();

    const float scale = 0.17677669529663687f;
    const int r = lane >> 2, jq = lane & 3;

    for (int mt = warp; mt < 13; mt += 4) {
        const int row0 = mt * 16 + r;

        float sacc[26][4];
        #pragma unroll
        for (int nt = 0; nt < 26; nt++)
            #pragma unroll
            for (int e = 0; e < 4; e++) sacc[nt][e] = 0.f;

        #pragma unroll
        for (int kt = 0; kt < 2; kt++) {
            const int kb = kt * 8 + jq;
            const uint32_t a0 = qs[row0 * QKS + kb];
            const uint32_t a1 = qs[(row0 + 8) * QKS + kb];
            const uint32_t a2 = qs[row0 * QKS + kb + 4];
            const uint32_t a3 = qs[(row0 + 8) * QKS + kb + 4];
            #pragma unroll
            for (int nt = 0; nt < 26; nt++) {
                const int kr = (nt * 8 + r) * QKS + kb;
                const uint32_t b0 = ks[kr];
                const uint32_t b1 = ks[kr + 4];
                mma_fp16(sacc[nt], a0, a1, a2, a3, b0, b1);
            }
        }

        float mx0 = -1e30f, mx1 = -1e30f;
        #pragma unroll
        for (int nt = 0; nt < 26; nt++) {
            #pragma unroll
            for (int idx = 0; idx < 4; idx++) {
                const int e = idx & 1, half = idx >> 1;
                const int col = nt * 8 + 2 * jq + e;
                const int row = row0 + half * 8;
                float s;
                if (col < LL) {
                    s = (sacc[nt][idx] + bias_mat[row * LPAD + col]) * scale;
                } else {
                    s = -1e30f;
                }
                sacc[nt][idx] = s;
                if (half == 0) mx0 = fmaxf(mx0, s); else mx1 = fmaxf(mx1, s);
            }
        }
        mx0 = fmaxf(mx0, __shfl_xor_sync(0xffffffffu, mx0, 1));
        mx0 = fmaxf(mx0, __shfl_xor_sync(0xffffffffu, mx0, 2));
        mx1 = fmaxf(mx1, __shfl_xor_sync(0xffffffffu, mx1, 1));
        mx1 = fmaxf(mx1, __shfl_xor_sync(0xffffffffu, mx1, 2));

        float sum0 = 0.f, sum1 = 0.f;
        #pragma unroll
        for (int nt = 0; nt < 26; nt++) {
            #pragma unroll
            for (int idx = 0; idx < 4; idx++) {
                const int e = idx & 1, half = idx >> 1;
                const int col = nt * 8 + 2 * jq + e;
                float p = 0.f;
                if (col < LL) {
                    p = __expf(sacc[nt][idx] - (half ? mx1 : mx0));
                    if (half == 0) sum0 += p; else sum1 += p;
                }
                sacc[nt][idx] = p;
            }
        }
        sum0 += __shfl_xor_sync(0xffffffffu, sum0, 1);
        sum0 += __shfl_xor_sync(0xffffffffu, sum0, 2);
        sum1 += __shfl_xor_sync(0xffffffffu, sum1, 1);
        sum1 += __shfl_xor_sync(0xffffffffu, sum1, 2);
        const float inv0 = 1.0f / sum0, inv1 = 1.0f / sum1;

        float oacc[4][4];
        #pragma unroll
        for (int nt = 0; nt < 4; nt++)
            #pragma unroll
            for (int e = 0; e < 4; e++) oacc[nt][e] = 0.f;

        #pragma unroll
        for (int kt = 0; kt < 13; kt++) {
            const uint32_t a0 = h2u(sacc[2 * kt][0],     sacc[2 * kt][1]);
            const uint32_t a1 = h2u(sacc[2 * kt][2],     sacc[2 * kt][3]);
            const uint32_t a2 = h2u(sacc[2 * kt + 1][0], sacc[2 * kt + 1][1]);
            const uint32_t a3 = h2u(sacc[2 * kt + 1][2], sacc[2 * kt + 1][3]);
            const int kb = kt * 8 + jq;
            #pragma unroll
            for (int nt = 0; nt < 4; nt++) {
                const int vr = (nt * 8 + r) * VTS5 + kb;
                const uint32_t b0 = vT[vr];
                const uint32_t b1 = vT[vr + 4];
                mma_fp16(oacc[nt], a0, a1, a2, a3, b0, b1);
            }
        }

        #pragma unroll
        for (int nt = 0; nt < 4; nt++) {
            #pragma unroll
            for (int idx = 0; idx < 4; idx++) {
                const int e = idx & 1, half = idx >> 1;
                const int row = row0 + half * 8;
                const int col = nt * 8 + 2 * jq + e;
                if (row < LL) {
                    const float vv = oacc[nt][idx] * (half ? inv1 : inv0);
                    o[base + (size_t)row * HID + col] = __float2half_rn(vv);
                }
            }
        }
    }
}

// ------------------------------------------------------------ fp16 TC GEMM
// C[M,N] = A[M,K] @ B[N,K]^T (+bias); ldmatrix fragments, 3-stage cp.async
// pipeline, ONE __syncthreads per k-tile. 256 threads, 128x128x32 tile.
//   mode 1: exact gelu -> Ch (half)    mode 2: (resid + val) * rate -> Cf
#define PSTR 20                        // uint32 stride per smem row
#define STAGE_U32 (2 * 128 * PSTR)     // 5120 u32 = 20 KB per stage

__global__ __launch_bounds__(256, 2) void gemm_fp16_kernel(
    const __half* __restrict__ A, const __half* __restrict__ B,
    const float* __restrict__ bias, const float* __restrict__ resid,
    float* __restrict__ Cf, __half* __restrict__ Ch,
    int M, int N, int K, int mode, float rate)
{
    extern __shared__ uint32_t smh[];
    const int tid  = threadIdx.x;
    const int lane = tid & 31, warp = tid >> 5;
    const int wr = warp >> 1, wc = warp & 1;
    const int bm = blockIdx.y * 128, bn = blockIdx.x * 128;

    const uint32_t smem_base = (uint32_t)__cvta_generic_to_shared(smh);
    const int nTiles = K / 32;

    auto load_tile = [&](int kt, int s) {
        const __half* Ag = A + (size_t)bm * K + (size_t)kt * 32;
        const __half* Bg = B + (size_t)bn * K + (size_t)kt * 32;
        const uint32_t sA = smem_base + (uint32_t)(s * STAGE_U32) * 4u;
        const uint32_t sB = sA + (uint32_t)(128 * PSTR) * 4u;
        #pragma unroll
        for (int i = 0; i < 2; i++) {
            const int idx = i * 256 + tid;
            const int r = idx >> 2, c = idx & 3;
            CP_ASYNC16(sA + (uint32_t)(r * PSTR * 4 + c * 16), Ag + (size_t)r * K + c * 8);
            CP_ASYNC16(sB + (uint32_t)(r * PSTR * 4 + c * 16), Bg + (size_t)r * K + c * 8);
        }
    };

    float acc[2][8][4];
    #pragma unroll
    for (int i = 0; i < 2; i++)
        #pragma unroll
        for (int j = 0; j < 8; j++)
            #pragma unroll
            for (int r = 0; r < 4; r++) acc[i][j][r] = 0.f;

    // ldmatrix per-lane base offsets (u32 index within stage)
    const int lrow = lane & 15;
    const int lkg  = (lane >> 4) * 4;
    const uint32_t aOff = (uint32_t)((wr * 32 + lrow) * PSTR + lkg);
    const uint32_t bOff = (uint32_t)(128 * PSTR + (wc * 64 + lrow) * PSTR + lkg);

    load_tile(0, 0);
    asm volatile("cp.async.commit_group;\n");
    if (nTiles > 1) {
        load_tile(1, 1);
        asm volatile("cp.async.commit_group;\n");
    }

    for (int t = 0; t < nTiles; t++) {
        if (t + 1 < nTiles) {
            asm volatile("cp.async.wait_group 1;\n");
        } else {
            asm volatile("cp.async.wait_group 0;\n");
        }
        __syncthreads();

        const uint32_t sb = smem_base + (uint32_t)((t % 3) * STAGE_U32) * 4u;

        #pragma unroll
        for (int ks = 0; ks < 2; ks++) {
            uint32_t a[2][4], b[4][4];
            LDSM_X4(a[0], sb + (aOff + ks * 8) * 4u);
            LDSM_X4(a[1], sb + (aOff + 16 * PSTR + ks * 8) * 4u);
            #pragma unroll
            for (int ntp = 0; ntp < 4; ntp++)
                LDSM_X4(b[ntp], sb + (bOff + (uint32_t)(ntp * 16 * PSTR) + ks * 8) * 4u);
            #pragma unroll
            for (int mt = 0; mt < 2; mt++) {
                #pragma unroll
                for (int nt = 0; nt < 8; nt++) {
                    const int ntp = nt >> 1, e = nt & 1;
                    mma_fp16(acc[mt][nt], a[mt][0], a[mt][1], a[mt][2], a[mt][3],
                             b[ntp][e], b[ntp][2 + e]);
                }
            }
        }

        if (t + 2 < nTiles) {
            load_tile(t + 2, (t + 2) % 3);
            asm volatile("cp.async.commit_group;\n");
        }
    }

    // ------------------------------------------------------------- epilogue
    const int cRow0 = bm + wr * 32 + (lane >> 2);
    const int cCol0 = bn + wc * 64 + 2 * (lane & 3);
    #pragma unroll
    for (int mt = 0; mt < 2; mt++) {
        #pragma unroll
        for (int nt = 0; nt < 8; nt++) {
            #pragma unroll
            for (int half = 0; half < 2; half++) {
                const int row = cRow0 + mt * 16 + half * 8;
                #pragma unroll
                for (int e = 0; e < 2; e++) {
                    const int col = cCol0 + nt * 8 + e;
                    float vv = acc[mt][nt][half * 2 + e];
                    if (bias) vv += bias[col];
                    if (mode == 1) {
                        vv = 0.5f * vv * (1.0f + erff(vv * 0.70710678118654752f));
                        Ch[(size_t)row * N + col] = __float2half_rn(vv);
                    } else {
                        vv = (resid[(size_t)row * N + col] + vv) * rate;
                        Cf[(size_t)row * N + col] = vv;
                    }
                }
            }
        }
    }
}

// --------------------------------------------------------------------- host
extern "C" void kernel_launch(void* const* d_in, const int* in_sizes, int n_in,
                              void* d_out, int out_size)
{
    const float* x        = (const float*)d_in[0];
    const float* rel_bias = (const float*)d_in[1];
    const float* wq       = (const float*)d_in[2];
    const float* wk       = (const float*)d_in[3];
    const float* wv       = (const float*)d_in[4];
    const float* w_out    = (const float*)d_in[5];
    const float* ln1_g    = (const float*)d_in[6];
    const float* ln1_b    = (const float*)d_in[7];
    const float* ln2_g    = (const float*)d_in[8];
    const float* ln2_b    = (const float*)d_in[9];
    const float* w1       = (const float*)d_in[10];
    const float* b1       = (const float*)d_in[11];
    const float* w2       = (const float*)d_in[12];
    const float* b2       = (const float*)d_in[13];
    float* out = (float*)d_out;

    float *p_bias;
    __half *p_qh, *p_kh, *p_vh, *p_oh, *p_lnh, *p_hh, *p_wouth, *p_w1h, *p_w2h;
    cudaGetSymbolAddress((void**)&p_bias, g_bias);
    cudaGetSymbolAddress((void**)&p_qh, g_qh);
    cudaGetSymbolAddress((void**)&p_kh, g_kh);
    cudaGetSymbolAddress((void**)&p_vh, g_vh);
    cudaGetSymbolAddress((void**)&p_oh,  g_oh);
    cudaGetSymbolAddress((void**)&p_lnh, g_lnh);
    cudaGetSymbolAddress((void**)&p_hh,  g_hh);
    cudaGetSymbolAddress((void**)&p_wouth, g_wouth);
    cudaGetSymbolAddress((void**)&p_w1h, g_w1h);
    cudaGetSymbolAddress((void**)&p_w2h, g_w2h);

    const int attn_smem = (2 * LPAD * QKS + 32 * VTS5) * 4;   // 47104
    cudaFuncSetAttribute(attn_fp16_kernel,
                         cudaFuncAttributeMaxDynamicSharedMemorySize, attn_smem);
    const int gemm_smem = 3 * STAGE_U32 * 4;                  // 61440
    cudaFuncSetAttribute(gemm_fp16_kernel,
                         cudaFuncAttributeMaxDynamicSharedMemorySize, gemm_smem);

    // 0) prep: fp16 weights, bias matrix
    conv_w_kernel<<<(HID * HID + 255) / 256, 256>>>(w_out, p_wouth, HID * HID);
    conv_w_kernel<<<(FF * HID + 255) / 256, 256>>>(w1, p_w1h, FF * HID);
    conv_w_kernel<<<(HID * FF + 255) / 256, 256>>>(w2, p_w2h, HID * FF);
    bias_init_kernel<<<(LPAD * LPAD + 255) / 256, 256>>>(rel_bias, p_bias);

    // 1) fused ln1 + q/k/v projections (fp16 out)
    ln_qkv_kernel<<<M_ROWS, 256>>>(x, ln1_g, ln1_b, wq, wk, wv, p_qh, p_kh, p_vh);
    // 2) fp16 tensor-core attention -> fp16 o
    attn_fp16_kernel<<<NB * NH, 128, attn_smem>>>(p_qh, p_kh, p_vh, p_bias, p_oh);
    // 3) output projection + residual + rate -> d_out holds x1 (fp32)
    {
        dim3 grid(HID / 128, M_ROWS / 128);
        gemm_fp16_kernel<<<grid, 256, gemm_smem>>>(p_oh, p_wouth, nullptr, x,
                                                   out, nullptr,
                                                   M_ROWS, HID, HID, 2, RATE_F);
    }
    // 4) ln2 -> fp16
    ln_kernel<<<M_ROWS, 256>>>(out, ln2_g, ln2_b, p_lnh);
    // 5) ffn1 + gelu -> fp16 hidden
    {
        dim3 grid(FF / 128, M_ROWS / 128);
        gemm_fp16_kernel<<<grid, 256, gemm_smem>>>(p_lnh, p_w1h, b1, nullptr,
                                                   nullptr, p_hh,
                                                   M_ROWS, FF, HID, 1, 0.f);
    }
    // 6) ffn2 + residual + rate -> d_out final (fp32)
    {
        dim3 grid(HID / 128, M_ROWS / 128);
        gemm_fp16_kernel<<<grid, 256, gemm_smem>>>(p_hh, p_w2h, b2, out,
                                                   out, nullptr,
                                                   M_ROWS, HID, FF, 2, RATE_F);
    }
}